// round 14
// baseline (speedup 1.0000x reference)
#include <cuda_runtime.h>
#include <cuda_fp16.h>
#include <cstdint>

#define HID 256
#define NH 4
#define DH 64
#define N_MOLS 2048
#define MAX_LEN 128
#define MAX_TOTAL (1 + N_MOLS * MAX_LEN)

// Scratch (device globals: allocation-free rule). Zero-initialized at load.
__device__ unsigned short g_Xh_u[(size_t)MAX_TOTAL * HID];   // msg fp16
__device__ unsigned short g_Qh_u[(size_t)MAX_TOTAL * HID];
__device__ unsigned short g_Kh_u[(size_t)MAX_TOTAL * HID];
__device__ unsigned short g_Vh_u[(size_t)MAX_TOTAL * HID];
__device__ unsigned short g_Oh_u[(size_t)MAX_TOTAL * HID];
__device__ unsigned short g_Wh_u[4 * HID * HID];             // Wq,Wk,Wv,Wo fp16

#define g_Xh ((__half*)g_Xh_u)
#define g_Qh ((__half*)g_Qh_u)
#define g_Kh ((__half*)g_Kh_u)
#define g_Vh ((__half*)g_Vh_u)
#define g_Oh ((__half*)g_Oh_u)
#define g_Wh ((__half*)g_Wh_u)

// ============================ helpers =======================================
__device__ __forceinline__ uint32_t smem_u32(const void* p) {
    uint32_t a;
    asm("{ .reg .u64 t; cvta.to.shared.u64 t, %1; cvt.u32.u64 %0, t; }"
        : "=r"(a) : "l"(p));
    return a;
}
__device__ __forceinline__ uint32_t h2u(__half2 h) {
    return *reinterpret_cast<uint32_t*>(&h);
}
__device__ __forceinline__ uint4 cvt8(float4 v0, float4 v1) {
    uint4 w;
    w.x = h2u(__floats2half2_rn(v0.x, v0.y));
    w.y = h2u(__floats2half2_rn(v0.z, v0.w));
    w.z = h2u(__floats2half2_rn(v1.x, v1.y));
    w.w = h2u(__floats2half2_rn(v1.z, v1.w));
    return w;
}

#define CP16(dst, src) \
    asm volatile("cp.async.cg.shared.global [%0], [%1], 16;" \
                 :: "r"(dst), "l"(src) : "memory")
#define CP_COMMIT \
    asm volatile("cp.async.commit_group;" ::: "memory")
#define CP_WAIT(n) \
    asm volatile("cp.async.wait_group %0;" :: "n"(n) : "memory")
#define CP_COMMIT_WAIT \
    asm volatile("cp.async.commit_group;\n\tcp.async.wait_group 0;" ::: "memory")

#define LDMX4(r, addr) \
    asm volatile("ldmatrix.sync.aligned.m8n8.x4.shared.b16 {%0,%1,%2,%3}, [%4];" \
                 : "=r"((r)[0]), "=r"((r)[1]), "=r"((r)[2]), "=r"((r)[3]) \
                 : "r"(addr))

#define LDMX4T(r, addr) \
    asm volatile("ldmatrix.sync.aligned.m8n8.x4.trans.shared.b16 {%0,%1,%2,%3}, [%4];" \
                 : "=r"((r)[0]), "=r"((r)[1]), "=r"((r)[2]), "=r"((r)[3]) \
                 : "r"(addr))

#define MMA16816(d, a, b) \
    asm volatile("mma.sync.aligned.m16n8k16.row.col.f32.f16.f16.f32 " \
                 "{%0,%1,%2,%3}, {%4,%5,%6,%7}, {%8,%9}, {%0,%1,%2,%3};" \
                 : "+f"((d)[0]), "+f"((d)[1]), "+f"((d)[2]), "+f"((d)[3]) \
                 : "r"((a)[0]), "r"((a)[1]), "r"((a)[2]), "r"((a)[3]), \
                   "r"((b)[0]), "r"((b)[1]))

// ======================= conversion kernels =================================
__global__ void __launch_bounds__(512)
cvt_msg_kernel(const float* __restrict__ msg, int total) {
    const int idx = blockIdx.x * 512 + threadIdx.x;   // one per 8 floats
    const int n = total * (HID / 8);
    if (idx >= n) return;
    const float4* p = (const float4*)msg + (size_t)idx * 2;
    ((uint4*)g_Xh)[idx] = cvt8(p[0], p[1]);
}

__global__ void __launch_bounds__(256)
cvt_w_kernel(const float* __restrict__ Wq, const float* __restrict__ Wk,
             const float* __restrict__ Wv, const float* __restrict__ Wo) {
    const int idx = blockIdx.x * 256 + threadIdx.x;   // 4*8192 groups of 8
    const int mat = idx >> 13;
    const int off = idx & 8191;
    const float* W = (mat == 0) ? Wq : (mat == 1 ? Wk : (mat == 2 ? Wv : Wo));
    const float4* p = (const float4*)W + (size_t)off * 2;
    ((uint4*)(g_Wh + mat * HID * HID))[off] = cvt8(p[0], p[1]);
}

// ======================= QKV GEMM (fp16 in, fp16 out) =======================
// Out[r][c] = sum_k X[r][k] * W[c][k]; 128x128 tile, 256 thr, warp 64x32.
// BK=64, 4 chunks, double-buffered cp.async (2 stages x (A+B) 72-stride).
#define LDC 72
#define CHUNK_HALVES (128 * LDC)
#define GEMM_SMEM (4 * CHUNK_HALVES * 2)   // 73728 B

__global__ void __launch_bounds__(256, 2)
qkv_mma_kernel(int total) {
    extern __shared__ __half sh[];

    const int bx = blockIdx.x;            // 0..5 fastest -> X-tile L2 reuse
    const int mat = bx >> 1;
    const int c0 = (bx & 1) * 128;
    const __half* __restrict__ Ah = g_Xh;
    const __half* __restrict__ Wh = g_Wh + mat * HID * HID;
    __half* __restrict__ OutH = (mat == 0) ? g_Qh : (mat == 1 ? g_Kh : g_Vh);
    const int row0 = blockIdx.y * 128;

    const int tid = threadIdx.x;
    const int lane = tid & 31;
    const int wid = tid >> 5;

    float acc[4][4][4];
#pragma unroll
    for (int f = 0; f < 4; f++)
#pragma unroll
        for (int j = 0; j < 4; j++)
#pragma unroll
            for (int e = 0; e < 4; e++) acc[f][j][e] = 0.f;

    const int srow = tid >> 1;            // 0..127
    const int sseg = (tid & 1) * 32;      // 32-half segment of the 64-chunk
    const uint32_t base0 = smem_u32(sh);
    const uint32_t stageA0 = base0;
    const uint32_t stageA1 = base0 + CHUNK_HALVES * 2;
    const uint32_t stageB0 = base0 + 2 * CHUNK_HALVES * 2;
    const uint32_t stageB1 = base0 + 3 * CHUNK_HALVES * 2;
    const uint32_t dOffs = (uint32_t)((srow * LDC + sseg) * 2);
    const __half* srcA = Ah + (size_t)(row0 + srow) * HID + sseg;
    const __half* srcB = Wh + (size_t)(c0 + srow) * HID + sseg;

    const int warp_m = (wid >> 2) * 64;
    const int warp_n = (wid & 3) * 32;
    const uint32_t aOff = (uint32_t)(((lane & 15) * LDC + (lane >> 4) * 8) * 2);
    const uint32_t bRow = (uint32_t)(((lane >> 4) << 3) + (lane & 7));
    const uint32_t bCol = (uint32_t)(((lane >> 3) & 1) * 8);

    // prologue: prefetch chunks 0 and 1
#pragma unroll
    for (int c = 0; c < 2; c++) {
        const uint32_t dA = (c == 0 ? stageA0 : stageA1) + dOffs;
        const uint32_t dB = (c == 0 ? stageB0 : stageB1) + dOffs;
#pragma unroll
        for (int j = 0; j < 4; j++) {     // 32 halves = 4 x 16B
            CP16(dA + j * 16, srcA + c * 64 + j * 8);
            CP16(dB + j * 16, srcB + c * 64 + j * 8);
        }
        CP_COMMIT;
    }

#pragma unroll
    for (int c = 0; c < 4; c++) {
        if (c < 3) CP_WAIT(1); else CP_WAIT(0);
        __syncthreads();

        const uint32_t aB = (c & 1) ? stageA1 : stageA0;
        const uint32_t bB = (c & 1) ? stageB1 : stageB0;

#pragma unroll
        for (int ks = 0; ks < 4; ks++) {
            uint32_t a[4][4];
            uint32_t b[4][2];
#pragma unroll
            for (int f = 0; f < 4; f++) {
                uint32_t addr = aB +
                    (uint32_t)(((warp_m + f * 16) * LDC + ks * 16) * 2) + aOff;
                LDMX4(a[f], addr);
            }
#pragma unroll
            for (int g = 0; g < 2; g++) {
                uint32_t addr = bB +
                    (uint32_t)(((warp_n + g * 16 + bRow) * LDC +
                                ks * 16 + bCol) * 2);
                uint32_t r[4];
                LDMX4(r, addr);
                b[2 * g][0] = r[0]; b[2 * g][1] = r[1];
                b[2 * g + 1][0] = r[2]; b[2 * g + 1][1] = r[3];
            }
#pragma unroll
            for (int f = 0; f < 4; f++)
#pragma unroll
                for (int j = 0; j < 4; j++)
                    MMA16816(acc[f][j], a[f], b[j]);
        }
        __syncthreads();

        if (c + 2 < 4) {
            const uint32_t dA = ((c & 1) ? stageA1 : stageA0) + dOffs;
            const uint32_t dB = ((c & 1) ? stageB1 : stageB0) + dOffs;
#pragma unroll
            for (int j = 0; j < 4; j++) {
                CP16(dA + j * 16, srcA + (c + 2) * 64 + j * 8);
                CP16(dB + j * 16, srcB + (c + 2) * 64 + j * 8);
            }
            CP_COMMIT;
        }
    }

#pragma unroll
    for (int f = 0; f < 4; f++) {
        const int row_lo = row0 + warp_m + f * 16 + (lane >> 2);
        const int row_hi = row_lo + 8;
#pragma unroll
        for (int j = 0; j < 4; j++) {
            const int col = c0 + warp_n + j * 8 + (lane & 3) * 2;
            if (row_lo < total)
                *(__half2*)(OutH + (size_t)row_lo * HID + col) =
                    __floats2half2_rn(acc[f][j][0], acc[f][j][1]);
            if (row_hi < total)
                *(__half2*)(OutH + (size_t)row_hi * HID + col) =
                    __floats2half2_rn(acc[f][j][2], acc[f][j][3]);
        }
    }
}

// ================ Flash attention (HMMA, online softmax) ====================
// CTA = (mol, head); 8 warps x 16 query rows; 32-key chunks.
// Staging is UNGUARDED cp.async: rows >= S are other molecules' (finite) data;
// key garbage is masked to -1e30 pre-softmax, V garbage is scaled by p=0,
// query garbage is never stored. All reads stay inside the static arrays.
#define LDQ 72
#define LDK 72
#define LDV 72
#define ATTN_SMEM (3 * 128 * LDQ * 2)

__global__ void __launch_bounds__(256, 3)
attn_mma_kernel(const int* __restrict__ b_starts,
                const int* __restrict__ b_sizes) {
    extern __shared__ __half ash[];
    __half* qS = ash;
    __half* kS = ash + 128 * LDQ;
    __half* vS = ash + 2 * 128 * LDQ;

    const int m = blockIdx.x;
    const int h = blockIdx.y;
    const int S = b_sizes[m];
    const int start = b_starts[m];
    const int tid = threadIdx.x;
    const int lane = tid & 31;
    const int wid = tid >> 5;          // 0..7

    const uint32_t qBase = smem_u32(qS);
    const uint32_t kBase = smem_u32(kS);
    const uint32_t vBase = smem_u32(vS);

    // ---- stage Q, K, V row-major via cp.async (no guards) ----
    {
        const int tok = tid >> 1;
        const int seg = (tid & 1) * 32;
        const __half* qp = g_Qh + (size_t)(start + tok) * HID + h * DH + seg;
        const __half* kp = g_Kh + (size_t)(start + tok) * HID + h * DH + seg;
        const __half* vp = g_Vh + (size_t)(start + tok) * HID + h * DH + seg;
        const uint32_t dOff = (uint32_t)((tok * LDQ + seg) * 2);
#pragma unroll
        for (int j = 0; j < 4; j++) {       // 32 halves = 4 x 16B each
            CP16(qBase + dOff + j * 16, qp + j * 8);
            CP16(kBase + dOff + j * 16, kp + j * 8);
            CP16(vBase + dOff + j * 16, vp + j * 8);
        }
        CP_COMMIT_WAIT;
    }
    __syncthreads();

    const int wq0 = wid * 16;
    if (wq0 >= S) return;   // idle query warps exit (no more barriers below)

    const uint32_t aOff = (uint32_t)(((lane & 15) * LDQ + (lane >> 4) * 8) * 2);
    const uint32_t bRow = (uint32_t)(((lane >> 4) << 3) + (lane & 7));
    const uint32_t bCol = (uint32_t)(((lane >> 3) & 1) * 8);
    // trans-load lane map for V: k-row and n(d)-offset
    const uint32_t vRow = (uint32_t)((lane & 7) + ((lane >> 3) & 1) * 8);
    const uint32_t vCol = (uint32_t)((lane >> 4) * 8);

    float oa[8][4];
#pragma unroll
    for (int dt = 0; dt < 8; dt++)
#pragma unroll
        for (int e = 0; e < 4; e++) oa[dt][e] = 0.f;
    float mx0 = -3.0e38f, mx1 = -3.0e38f;
    float ls0 = 0.f, ls1 = 0.f;

    const int nchunks = (S + 31) >> 5;
    for (int ch = 0; ch < nchunks; ch++) {
        const int key0 = ch * 32;

        float sacc[4][4];
#pragma unroll
        for (int n = 0; n < 4; n++)
#pragma unroll
            for (int e = 0; e < 4; e++) sacc[n][e] = 0.f;

#pragma unroll
        for (int kd = 0; kd < 4; kd++) {
            uint32_t qA[4];
            {
                uint32_t addr = qBase +
                    (uint32_t)((wq0 * LDQ + kd * 16) * 2) + aOff;
                LDMX4(qA, addr);
            }
            uint32_t bK[4][2];
#pragma unroll
            for (int g = 0; g < 2; g++) {
                uint32_t addr = kBase +
                    (uint32_t)(((key0 + g * 16 + bRow) * LDK + kd * 16 + bCol) * 2);
                uint32_t r[4];
                LDMX4(r, addr);
                bK[2 * g][0] = r[0]; bK[2 * g][1] = r[1];
                bK[2 * g + 1][0] = r[2]; bK[2 * g + 1][1] = r[3];
            }
#pragma unroll
            for (int n = 0; n < 4; n++)
                MMA16816(sacc[n], qA, bK[n]);
        }

        // ---- online softmax (rows lane>>2 and +8 of this 16-row block) ----
        uint32_t pA[2][4];
        {
            float sv[4][4];
#pragma unroll
            for (int n = 0; n < 4; n++) {
                const int cb = key0 + n * 8 + (lane & 3) * 2;
                const bool k0ok = cb < S;
                const bool k1ok = (cb + 1) < S;
                sv[n][0] = k0ok ? sacc[n][0] * 0.125f : -1.0e30f;
                sv[n][1] = k1ok ? sacc[n][1] * 0.125f : -1.0e30f;
                sv[n][2] = k0ok ? sacc[n][2] * 0.125f : -1.0e30f;
                sv[n][3] = k1ok ? sacc[n][3] * 0.125f : -1.0e30f;
            }
            float m0 = -3.0e38f, m1 = -3.0e38f;
#pragma unroll
            for (int n = 0; n < 4; n++) {
                m0 = fmaxf(m0, fmaxf(sv[n][0], sv[n][1]));
                m1 = fmaxf(m1, fmaxf(sv[n][2], sv[n][3]));
            }
            m0 = fmaxf(m0, __shfl_xor_sync(0xffffffffu, m0, 1));
            m0 = fmaxf(m0, __shfl_xor_sync(0xffffffffu, m0, 2));
            m1 = fmaxf(m1, __shfl_xor_sync(0xffffffffu, m1, 1));
            m1 = fmaxf(m1, __shfl_xor_sync(0xffffffffu, m1, 2));
            const float nm0 = fmaxf(mx0, m0);
            const float nm1 = fmaxf(mx1, m1);
            const float sc0 = __expf(mx0 - nm0);
            const float sc1 = __expf(mx1 - nm1);
            mx0 = nm0; mx1 = nm1;

            float e[4][4];
            float s0 = 0.f, s1 = 0.f;
#pragma unroll
            for (int n = 0; n < 4; n++) {
                e[n][0] = __expf(sv[n][0] - nm0);
                e[n][1] = __expf(sv[n][1] - nm0);
                e[n][2] = __expf(sv[n][2] - nm1);
                e[n][3] = __expf(sv[n][3] - nm1);
                s0 += e[n][0] + e[n][1];
                s1 += e[n][2] + e[n][3];
            }
            s0 += __shfl_xor_sync(0xffffffffu, s0, 1);
            s0 += __shfl_xor_sync(0xffffffffu, s0, 2);
            s1 += __shfl_xor_sync(0xffffffffu, s1, 1);
            s1 += __shfl_xor_sync(0xffffffffu, s1, 2);
            ls0 = ls0 * sc0 + s0;
            ls1 = ls1 * sc1 + s1;

#pragma unroll
            for (int dt = 0; dt < 8; dt++) {
                oa[dt][0] *= sc0; oa[dt][1] *= sc0;
                oa[dt][2] *= sc1; oa[dt][3] *= sc1;
            }
#pragma unroll
            for (int kk = 0; kk < 2; kk++) {
                pA[kk][0] = h2u(__floats2half2_rn(e[2 * kk][0], e[2 * kk][1]));
                pA[kk][1] = h2u(__floats2half2_rn(e[2 * kk][2], e[2 * kk][3]));
                pA[kk][2] = h2u(__floats2half2_rn(e[2 * kk + 1][0], e[2 * kk + 1][1]));
                pA[kk][3] = h2u(__floats2half2_rn(e[2 * kk + 1][2], e[2 * kk + 1][3]));
            }
        }

        // ---- O += P @ V  (B-fragments via ldmatrix.trans on row-major V) ----
#pragma unroll
        for (int kk = 0; kk < 2; kk++) {
            uint32_t bV[8][2];
#pragma unroll
            for (int g = 0; g < 4; g++) {
                uint32_t addr = vBase +
                    (uint32_t)(((key0 + kk * 16 + vRow) * LDV + g * 16 + vCol) * 2);
                uint32_t r[4];
                LDMX4T(r, addr);
                bV[2 * g][0] = r[0]; bV[2 * g][1] = r[1];
                bV[2 * g + 1][0] = r[2]; bV[2 * g + 1][1] = r[3];
            }
#pragma unroll
            for (int dt = 0; dt < 8; dt++)
                MMA16816(oa[dt], pA[kk], bV[dt]);
        }
    }

    // ---- store: ReLU(o / l) -> g_Oh ----
    {
        const float i0 = 1.0f / ls0;
        const float i1 = 1.0f / ls1;
        const int r = wq0 + (lane >> 2);
        const bool ok0 = r < S;
        const bool ok1 = (r + 8) < S;
#pragma unroll
        for (int dt = 0; dt < 8; dt++) {
            const int c = h * DH + dt * 8 + (lane & 3) * 2;
            if (ok0)
                *(__half2*)(g_Oh + (size_t)(start + r) * HID + c) =
                    __floats2half2_rn(fmaxf(oa[dt][0] * i0, 0.f),
                                      fmaxf(oa[dt][1] * i0, 0.f));
            if (ok1)
                *(__half2*)(g_Oh + (size_t)(start + r + 8) * HID + c) =
                    __floats2half2_rn(fmaxf(oa[dt][2] * i1, 0.f),
                                      fmaxf(oa[dt][3] * i1, 0.f));
        }
    }
}

// ============== Output projection + fused LayerNorm =========================
// 512 threads, 16 warps (4m x 4n), warp tile 32x64, BN=256 (full row / CTA).
// Both 128-K chunks double-buffered via cp.async (prefetched in prologue).
#define LDA 136
#define ST_HALVES ((128 + 256) * LDA)
#define PROJ_SMEM (2 * ST_HALVES * 2 + 4 * 128 * 2 * 4)

__global__ void __launch_bounds__(512, 1)
proj_ln_kernel(const float* __restrict__ bo,
               const float* __restrict__ gamma,
               const float* __restrict__ beta,
               float* __restrict__ out,
               int total) {
    extern __shared__ __half sh[];
    float* rsum = (float*)(sh + 2 * ST_HALVES);   // [4][128]
    float* rsq  = rsum + 4 * 128;                 // [4][128]

    const int row0 = blockIdx.x * 128;
    const int tid = threadIdx.x;
    const int lane = tid & 31;
    const int wid = tid >> 5;
    const __half* __restrict__ Wo16 = g_Wh + 3 * HID * HID;

    float acc[2][8][4];
#pragma unroll
    for (int f = 0; f < 2; f++)
#pragma unroll
        for (int j = 0; j < 8; j++)
#pragma unroll
            for (int e = 0; e < 4; e++) acc[f][j][e] = 0.f;

    const uint32_t sBase = smem_u32(sh);
    // A staging: thread -> row tid>>2, seg tid&3 (32 halves = 4 x 16B)
    const int arow = tid >> 2, aseg = tid & 3;
    const uint32_t aD = (uint32_t)((arow * LDA + aseg * 32) * 2);
    const __half* srcA = g_Oh + (size_t)(row0 + arow) * HID + aseg * 32;
    // B staging: thread -> row tid>>1, seg tid&1 (64 halves = 8 x 16B)
    const int brow = tid >> 1, bseg = tid & 1;
    const uint32_t bD = (uint32_t)((brow * LDA + bseg * 64) * 2) + 128 * LDA * 2;
    const __half* srcB = Wo16 + (size_t)brow * HID + bseg * 64;

    const int warp_m = (wid >> 2) * 32;
    const int warp_n = (wid & 3) * 64;
    const uint32_t aOff = (uint32_t)(((lane & 15) * LDA + (lane >> 4) * 8) * 2);
    const uint32_t bRow = (uint32_t)(((lane >> 4) << 3) + (lane & 7));
    const uint32_t bCol = (uint32_t)(((lane >> 3) & 1) * 8);

    // prologue: prefetch BOTH chunks (stages 0 and 1)
#pragma unroll
    for (int c = 0; c < 2; c++) {
        const uint32_t st = sBase + (uint32_t)(c * ST_HALVES * 2);
#pragma unroll
        for (int j = 0; j < 4; j++)
            CP16(st + aD + j * 16, srcA + c * 128 + j * 8);
#pragma unroll
        for (int j = 0; j < 8; j++)
            CP16(st + bD + j * 16, srcB + c * 128 + j * 8);
        CP_COMMIT;
    }

#pragma unroll
    for (int kc = 0; kc < 2; kc++) {
        if (kc == 0) CP_WAIT(1); else CP_WAIT(0);
        __syncthreads();

        const uint32_t aBase = sBase + (uint32_t)(kc * ST_HALVES * 2);
        const uint32_t bBase = aBase + 128 * LDA * 2;

#pragma unroll
        for (int ks = 0; ks < 8; ks++) {
            uint32_t a[2][4];
            uint32_t b[8][2];
#pragma unroll
            for (int f = 0; f < 2; f++) {
                uint32_t addr = aBase +
                    (uint32_t)(((warp_m + f * 16) * LDA + ks * 16) * 2) + aOff;
                LDMX4(a[f], addr);
            }
#pragma unroll
            for (int g = 0; g < 4; g++) {
                uint32_t addr = bBase +
                    (uint32_t)(((warp_n + g * 16 + bRow) * LDA +
                                ks * 16 + bCol) * 2);
                uint32_t r[4];
                LDMX4(r, addr);
                b[2 * g][0] = r[0]; b[2 * g][1] = r[1];
                b[2 * g + 1][0] = r[2]; b[2 * g + 1][1] = r[3];
            }
#pragma unroll
            for (int f = 0; f < 2; f++)
#pragma unroll
                for (int j = 0; j < 8; j++)
                    MMA16816(acc[f][j], a[f], b[j]);
        }
    }

    // ---- bias add + per-row partial sums ----
#pragma unroll
    for (int f = 0; f < 2; f++) {
        float sl = 0.f, ql = 0.f, shg = 0.f, qh = 0.f;
#pragma unroll
        for (int j = 0; j < 8; j++) {
            const int col = warp_n + j * 8 + (lane & 3) * 2;
            float2 bb = *(const float2*)(bo + col);
            acc[f][j][0] += bb.x; acc[f][j][1] += bb.y;
            acc[f][j][2] += bb.x; acc[f][j][3] += bb.y;
            sl += acc[f][j][0] + acc[f][j][1];
            ql += acc[f][j][0] * acc[f][j][0] + acc[f][j][1] * acc[f][j][1];
            shg += acc[f][j][2] + acc[f][j][3];
            qh += acc[f][j][2] * acc[f][j][2] + acc[f][j][3] * acc[f][j][3];
        }
        sl += __shfl_xor_sync(0xffffffffu, sl, 1);
        sl += __shfl_xor_sync(0xffffffffu, sl, 2);
        ql += __shfl_xor_sync(0xffffffffu, ql, 1);
        ql += __shfl_xor_sync(0xffffffffu, ql, 2);
        shg += __shfl_xor_sync(0xffffffffu, shg, 1);
        shg += __shfl_xor_sync(0xffffffffu, shg, 2);
        qh += __shfl_xor_sync(0xffffffffu, qh, 1);
        qh += __shfl_xor_sync(0xffffffffu, qh, 2);
        if ((lane & 3) == 0) {
            const int nw = wid & 3;
            const int rlo = warp_m + f * 16 + (lane >> 2);
            rsum[nw * 128 + rlo] = sl;
            rsq[nw * 128 + rlo] = ql;
            rsum[nw * 128 + rlo + 8] = shg;
            rsq[nw * 128 + rlo + 8] = qh;
        }
    }
    __syncthreads();

    // ---- LN + store ----
#pragma unroll
    for (int f = 0; f < 2; f++) {
        const int rlo = warp_m + f * 16 + (lane >> 2);
        const int rhi = rlo + 8;
        float s0 = rsum[rlo] + rsum[128 + rlo] + rsum[256 + rlo] + rsum[384 + rlo];
        float q0 = rsq[rlo] + rsq[128 + rlo] + rsq[256 + rlo] + rsq[384 + rlo];
        float s1 = rsum[rhi] + rsum[128 + rhi] + rsum[256 + rhi] + rsum[384 + rhi];
        float q1 = rsq[rhi] + rsq[128 + rhi] + rsq[256 + rhi] + rsq[384 + rhi];
        const float mu0 = s0 * (1.f / 256.f);
        const float mu1 = s1 * (1.f / 256.f);
        const float rs0 = rsqrtf(fmaxf(q0 * (1.f / 256.f) - mu0 * mu0, 0.f) + 1e-5f);
        const float rs1 = rsqrtf(fmaxf(q1 * (1.f / 256.f) - mu1 * mu1, 0.f) + 1e-5f);
        const int g_lo = row0 + rlo;
        const int g_hi = row0 + rhi;
        const bool ok0 = g_lo < total;
        const bool ok1 = g_hi < total;
        const bool z0 = (g_lo == 0);
#pragma unroll
        for (int j = 0; j < 8; j++) {
            const int col = warp_n + j * 8 + (lane & 3) * 2;
            float2 gg = *(const float2*)(gamma + col);
            float2 be = *(const float2*)(beta + col);
            if (ok0) {
                float2 v;
                if (z0) { v.x = 0.f; v.y = 0.f; }
                else {
                    v.x = (acc[f][j][0] - mu0) * rs0 * gg.x + be.x;
                    v.y = (acc[f][j][1] - mu0) * rs0 * gg.y + be.y;
                }
                *(float2*)(out + (size_t)g_lo * HID + col) = v;
            }
            if (ok1) {
                float2 v;
                v.x = (acc[f][j][2] - mu1) * rs1 * gg.x + be.x;
                v.y = (acc[f][j][3] - mu1) * rs1 * gg.y + be.y;
                *(float2*)(out + (size_t)g_hi * HID + col) = v;
            }
        }
    }
}

// ---------------------------------------------------------------------------
extern "C" void kernel_launch(void* const* d_in, const int* in_sizes, int n_in,
                              void* d_out, int out_size) {
    const float* msg      = (const float*)d_in[0];
    const float* Wq       = (const float*)d_in[1];
    const float* Wk       = (const float*)d_in[2];
    const float* Wv       = (const float*)d_in[3];
    const float* Wo       = (const float*)d_in[4];
    const float* bo       = (const float*)d_in[5];
    const float* gamma    = (const float*)d_in[6];
    const float* beta     = (const float*)d_in[7];
    const int*   b_starts = (const int*)d_in[8];
    const int*   b_sizes  = (const int*)d_in[9];
    float* out = (float*)d_out;

    const int total = in_sizes[0] / HID;
    const int tiles = (total + 127) / 128;

    cudaFuncSetAttribute(qkv_mma_kernel,
                         cudaFuncAttributeMaxDynamicSharedMemorySize, GEMM_SMEM);
    cudaFuncSetAttribute(attn_mma_kernel,
                         cudaFuncAttributeMaxDynamicSharedMemorySize, ATTN_SMEM);
    cudaFuncSetAttribute(proj_ln_kernel,
                         cudaFuncAttributeMaxDynamicSharedMemorySize, PROJ_SMEM);

    cvt_msg_kernel<<<(total * (HID / 8) + 511) / 512, 512>>>(msg, total);
    cvt_w_kernel<<<128, 256>>>(Wq, Wk, Wv, Wo);

    dim3 ga(6, tiles);
    qkv_mma_kernel<<<ga, 256, GEMM_SMEM>>>(total);

    dim3 gb(N_MOLS, NH);
    attn_mma_kernel<<<gb, 256, ATTN_SMEM>>>(b_starts, b_sizes);

    proj_ln_kernel<<<tiles, 512, PROJ_SMEM>>>(bo, gamma, beta, out, total);
}

// round 15
// speedup vs baseline: 1.0004x; 1.0004x over previous
#include <cuda_runtime.h>
#include <cuda_fp16.h>
#include <cstdint>

#define HID 256
#define NH 4
#define DH 64
#define N_MOLS 2048
#define MAX_LEN 128
#define MAX_TOTAL (1 + N_MOLS * MAX_LEN)

// Scratch (device globals: allocation-free rule). Zero-initialized at load.
__device__ unsigned short g_Xh_u[(size_t)MAX_TOTAL * HID];   // msg fp16
__device__ unsigned short g_Qh_u[(size_t)MAX_TOTAL * HID];
__device__ unsigned short g_Kh_u[(size_t)MAX_TOTAL * HID];
__device__ unsigned short g_Vh_u[(size_t)MAX_TOTAL * HID];
__device__ unsigned short g_Oh_u[(size_t)MAX_TOTAL * HID];
__device__ unsigned short g_Wh_u[4 * HID * HID];             // Wq,Wk,Wv,Wo fp16

#define g_Xh ((__half*)g_Xh_u)
#define g_Qh ((__half*)g_Qh_u)
#define g_Kh ((__half*)g_Kh_u)
#define g_Vh ((__half*)g_Vh_u)
#define g_Oh ((__half*)g_Oh_u)
#define g_Wh ((__half*)g_Wh_u)

// ============================ helpers =======================================
__device__ __forceinline__ uint32_t smem_u32(const void* p) {
    uint32_t a;
    asm("{ .reg .u64 t; cvta.to.shared.u64 t, %1; cvt.u32.u64 %0, t; }"
        : "=r"(a) : "l"(p));
    return a;
}
__device__ __forceinline__ uint32_t h2u(__half2 h) {
    return *reinterpret_cast<uint32_t*>(&h);
}
__device__ __forceinline__ uint4 cvt8(float4 v0, float4 v1) {
    uint4 w;
    w.x = h2u(__floats2half2_rn(v0.x, v0.y));
    w.y = h2u(__floats2half2_rn(v0.z, v0.w));
    w.z = h2u(__floats2half2_rn(v1.x, v1.y));
    w.w = h2u(__floats2half2_rn(v1.z, v1.w));
    return w;
}

#define CP16(dst, src) \
    asm volatile("cp.async.cg.shared.global [%0], [%1], 16;" \
                 :: "r"(dst), "l"(src) : "memory")
#define CP16CA(dst, src) \
    asm volatile("cp.async.ca.shared.global [%0], [%1], 16;" \
                 :: "r"(dst), "l"(src) : "memory")
#define CP_COMMIT \
    asm volatile("cp.async.commit_group;" ::: "memory")
#define CP_WAIT(n) \
    asm volatile("cp.async.wait_group %0;" :: "n"(n) : "memory")
#define CP_COMMIT_WAIT \
    asm volatile("cp.async.commit_group;\n\tcp.async.wait_group 0;" ::: "memory")

#define LDMX4(r, addr) \
    asm volatile("ldmatrix.sync.aligned.m8n8.x4.shared.b16 {%0,%1,%2,%3}, [%4];" \
                 : "=r"((r)[0]), "=r"((r)[1]), "=r"((r)[2]), "=r"((r)[3]) \
                 : "r"(addr))

#define LDMX4T(r, addr) \
    asm volatile("ldmatrix.sync.aligned.m8n8.x4.trans.shared.b16 {%0,%1,%2,%3}, [%4];" \
                 : "=r"((r)[0]), "=r"((r)[1]), "=r"((r)[2]), "=r"((r)[3]) \
                 : "r"(addr))

#define MMA16816(d, a, b) \
    asm volatile("mma.sync.aligned.m16n8k16.row.col.f32.f16.f16.f32 " \
                 "{%0,%1,%2,%3}, {%4,%5,%6,%7}, {%8,%9}, {%0,%1,%2,%3};" \
                 : "+f"((d)[0]), "+f"((d)[1]), "+f"((d)[2]), "+f"((d)[3]) \
                 : "r"((a)[0]), "r"((a)[1]), "r"((a)[2]), "r"((a)[3]), \
                   "r"((b)[0]), "r"((b)[1]))

// ======================= conversion kernels =================================
__global__ void __launch_bounds__(512)
cvt_msg_kernel(const float* __restrict__ msg, int total) {
    const int idx = blockIdx.x * 512 + threadIdx.x;   // one per 8 floats
    const int n = total * (HID / 8);
    if (idx >= n) return;
    const float4* p = (const float4*)msg + (size_t)idx * 2;
    ((uint4*)g_Xh)[idx] = cvt8(p[0], p[1]);
}

__global__ void __launch_bounds__(256)
cvt_w_kernel(const float* __restrict__ Wq, const float* __restrict__ Wk,
             const float* __restrict__ Wv, const float* __restrict__ Wo) {
    const int idx = blockIdx.x * 256 + threadIdx.x;   // 4*8192 groups of 8
    const int mat = idx >> 13;
    const int off = idx & 8191;
    const float* W = (mat == 0) ? Wq : (mat == 1 ? Wk : (mat == 2 ? Wv : Wo));
    const float4* p = (const float4*)W + (size_t)off * 2;
    ((uint4*)(g_Wh + mat * HID * HID))[off] = cvt8(p[0], p[1]);
}

// ======================= QKV GEMM (fp16 in, fp16 out) =======================
// Out[r][c] = sum_k X[r][k] * W[c][k]; 128x128 tile, 256 thr, warp 64x32.
// BK=64, 4 chunks, double-buffered cp.async (2 stages x (A+B) 72-stride).
#define LDC 72
#define CHUNK_HALVES (128 * LDC)
#define GEMM_SMEM (4 * CHUNK_HALVES * 2)   // 73728 B

__global__ void __launch_bounds__(256, 2)
qkv_mma_kernel(int total) {
    extern __shared__ __half sh[];

    const int bx = blockIdx.x;            // 0..5 fastest -> X-tile L2 reuse
    const int mat = bx >> 1;
    const int c0 = (bx & 1) * 128;
    const __half* __restrict__ Ah = g_Xh;
    const __half* __restrict__ Wh = g_Wh + mat * HID * HID;
    __half* __restrict__ OutH = (mat == 0) ? g_Qh : (mat == 1 ? g_Kh : g_Vh);
    const int row0 = blockIdx.y * 128;

    const int tid = threadIdx.x;
    const int lane = tid & 31;
    const int wid = tid >> 5;

    float acc[4][4][4];
#pragma unroll
    for (int f = 0; f < 4; f++)
#pragma unroll
        for (int j = 0; j < 4; j++)
#pragma unroll
            for (int e = 0; e < 4; e++) acc[f][j][e] = 0.f;

    const int srow = tid >> 1;            // 0..127
    const int sseg = (tid & 1) * 32;      // 32-half segment of the 64-chunk
    const uint32_t base0 = smem_u32(sh);
    const uint32_t stageA0 = base0;
    const uint32_t stageA1 = base0 + CHUNK_HALVES * 2;
    const uint32_t stageB0 = base0 + 2 * CHUNK_HALVES * 2;
    const uint32_t stageB1 = base0 + 3 * CHUNK_HALVES * 2;
    const uint32_t dOffs = (uint32_t)((srow * LDC + sseg) * 2);
    const __half* srcA = Ah + (size_t)(row0 + srow) * HID + sseg;
    const __half* srcB = Wh + (size_t)(c0 + srow) * HID + sseg;

    const int warp_m = (wid >> 2) * 64;
    const int warp_n = (wid & 3) * 32;
    const uint32_t aOff = (uint32_t)(((lane & 15) * LDC + (lane >> 4) * 8) * 2);
    const uint32_t bRow = (uint32_t)(((lane >> 4) << 3) + (lane & 7));
    const uint32_t bCol = (uint32_t)(((lane >> 3) & 1) * 8);

    // prologue: prefetch chunks 0 and 1
#pragma unroll
    for (int c = 0; c < 2; c++) {
        const uint32_t dA = (c == 0 ? stageA0 : stageA1) + dOffs;
        const uint32_t dB = (c == 0 ? stageB0 : stageB1) + dOffs;
#pragma unroll
        for (int j = 0; j < 4; j++) {     // 32 halves = 4 x 16B
            CP16(dA + j * 16, srcA + c * 64 + j * 8);
            CP16(dB + j * 16, srcB + c * 64 + j * 8);
        }
        CP_COMMIT;
    }

#pragma unroll
    for (int c = 0; c < 4; c++) {
        if (c < 3) CP_WAIT(1); else CP_WAIT(0);
        __syncthreads();

        const uint32_t aB = (c & 1) ? stageA1 : stageA0;
        const uint32_t bB = (c & 1) ? stageB1 : stageB0;

#pragma unroll
        for (int ks = 0; ks < 4; ks++) {
            uint32_t a[4][4];
            uint32_t b[4][2];
#pragma unroll
            for (int f = 0; f < 4; f++) {
                uint32_t addr = aB +
                    (uint32_t)(((warp_m + f * 16) * LDC + ks * 16) * 2) + aOff;
                LDMX4(a[f], addr);
            }
#pragma unroll
            for (int g = 0; g < 2; g++) {
                uint32_t addr = bB +
                    (uint32_t)(((warp_n + g * 16 + bRow) * LDC +
                                ks * 16 + bCol) * 2);
                uint32_t r[4];
                LDMX4(r, addr);
                b[2 * g][0] = r[0]; b[2 * g][1] = r[1];
                b[2 * g + 1][0] = r[2]; b[2 * g + 1][1] = r[3];
            }
#pragma unroll
            for (int f = 0; f < 4; f++)
#pragma unroll
                for (int j = 0; j < 4; j++)
                    MMA16816(acc[f][j], a[f], b[j]);
        }
        __syncthreads();

        if (c + 2 < 4) {
            const uint32_t dA = ((c & 1) ? stageA1 : stageA0) + dOffs;
            const uint32_t dB = ((c & 1) ? stageB1 : stageB0) + dOffs;
#pragma unroll
            for (int j = 0; j < 4; j++) {
                CP16(dA + j * 16, srcA + (c + 2) * 64 + j * 8);
                CP16(dB + j * 16, srcB + (c + 2) * 64 + j * 8);
            }
            CP_COMMIT;
        }
    }

#pragma unroll
    for (int f = 0; f < 4; f++) {
        const int row_lo = row0 + warp_m + f * 16 + (lane >> 2);
        const int row_hi = row_lo + 8;
#pragma unroll
        for (int j = 0; j < 4; j++) {
            const int col = c0 + warp_n + j * 8 + (lane & 3) * 2;
            if (row_lo < total)
                *(__half2*)(OutH + (size_t)row_lo * HID + col) =
                    __floats2half2_rn(acc[f][j][0], acc[f][j][1]);
            if (row_hi < total)
                *(__half2*)(OutH + (size_t)row_hi * HID + col) =
                    __floats2half2_rn(acc[f][j][2], acc[f][j][3]);
        }
    }
}

// ================ Flash attention (HMMA, online softmax) ====================
// CTA = (mol, head); 8 warps x 16 query rows; 32-key chunks.
// Staging: UNGUARDED cp.async.ca (L1-allocating -> cross-CTA row reuse).
// Rows >= S are other molecules' (finite) data; key garbage masked to -1e30,
// V garbage scaled by p=0, garbage queries never stored. Always in-bounds.
#define LDQ 72
#define LDK 72
#define LDV 72
#define ATTN_SMEM (3 * 128 * LDQ * 2)

__global__ void __launch_bounds__(256, 3)
attn_mma_kernel(const int* __restrict__ b_starts,
                const int* __restrict__ b_sizes) {
    extern __shared__ __half ash[];
    __half* qS = ash;
    __half* kS = ash + 128 * LDQ;
    __half* vS = ash + 2 * 128 * LDQ;

    const int m = blockIdx.x;
    const int h = blockIdx.y;
    const int S = b_sizes[m];
    const int start = b_starts[m];
    const int tid = threadIdx.x;
    const int lane = tid & 31;
    const int wid = tid >> 5;          // 0..7

    const uint32_t qBase = smem_u32(qS);
    const uint32_t kBase = smem_u32(kS);
    const uint32_t vBase = smem_u32(vS);

    // ---- stage Q, K, V row-major via cp.async.ca (no guards) ----
    {
        const int tok = tid >> 1;
        const int seg = (tid & 1) * 32;
        const __half* qp = g_Qh + (size_t)(start + tok) * HID + h * DH + seg;
        const __half* kp = g_Kh + (size_t)(start + tok) * HID + h * DH + seg;
        const __half* vp = g_Vh + (size_t)(start + tok) * HID + h * DH + seg;
        const uint32_t dOff = (uint32_t)((tok * LDQ + seg) * 2);
#pragma unroll
        for (int j = 0; j < 4; j++) {       // 32 halves = 4 x 16B each
            CP16CA(qBase + dOff + j * 16, qp + j * 8);
            CP16CA(kBase + dOff + j * 16, kp + j * 8);
            CP16CA(vBase + dOff + j * 16, vp + j * 8);
        }
        CP_COMMIT_WAIT;
    }
    __syncthreads();

    const int wq0 = wid * 16;
    if (wq0 >= S) return;   // idle query warps exit (no more barriers below)

    const uint32_t aOff = (uint32_t)(((lane & 15) * LDQ + (lane >> 4) * 8) * 2);
    const uint32_t bRow = (uint32_t)(((lane >> 4) << 3) + (lane & 7));
    const uint32_t bCol = (uint32_t)(((lane >> 3) & 1) * 8);
    // trans-load lane map for V: k-row and n(d)-offset
    const uint32_t vRow = (uint32_t)((lane & 7) + ((lane >> 3) & 1) * 8);
    const uint32_t vCol = (uint32_t)((lane >> 4) * 8);

    float oa[8][4];
#pragma unroll
    for (int dt = 0; dt < 8; dt++)
#pragma unroll
        for (int e = 0; e < 4; e++) oa[dt][e] = 0.f;
    float mx0 = -3.0e38f, mx1 = -3.0e38f;
    float ls0 = 0.f, ls1 = 0.f;

    const int nchunks = (S + 31) >> 5;
    for (int ch = 0; ch < nchunks; ch++) {
        const int key0 = ch * 32;

        float sacc[4][4];
#pragma unroll
        for (int n = 0; n < 4; n++)
#pragma unroll
            for (int e = 0; e < 4; e++) sacc[n][e] = 0.f;

#pragma unroll
        for (int kd = 0; kd < 4; kd++) {
            uint32_t qA[4];
            {
                uint32_t addr = qBase +
                    (uint32_t)((wq0 * LDQ + kd * 16) * 2) + aOff;
                LDMX4(qA, addr);
            }
            uint32_t bK[4][2];
#pragma unroll
            for (int g = 0; g < 2; g++) {
                uint32_t addr = kBase +
                    (uint32_t)(((key0 + g * 16 + bRow) * LDK + kd * 16 + bCol) * 2);
                uint32_t r[4];
                LDMX4(r, addr);
                bK[2 * g][0] = r[0]; bK[2 * g][1] = r[1];
                bK[2 * g + 1][0] = r[2]; bK[2 * g + 1][1] = r[3];
            }
#pragma unroll
            for (int n = 0; n < 4; n++)
                MMA16816(sacc[n], qA, bK[n]);
        }

        // ---- online softmax (rows lane>>2 and +8 of this 16-row block) ----
        uint32_t pA[2][4];
        {
            float sv[4][4];
#pragma unroll
            for (int n = 0; n < 4; n++) {
                const int cb = key0 + n * 8 + (lane & 3) * 2;
                const bool k0ok = cb < S;
                const bool k1ok = (cb + 1) < S;
                sv[n][0] = k0ok ? sacc[n][0] * 0.125f : -1.0e30f;
                sv[n][1] = k1ok ? sacc[n][1] * 0.125f : -1.0e30f;
                sv[n][2] = k0ok ? sacc[n][2] * 0.125f : -1.0e30f;
                sv[n][3] = k1ok ? sacc[n][3] * 0.125f : -1.0e30f;
            }
            float m0 = -3.0e38f, m1 = -3.0e38f;
#pragma unroll
            for (int n = 0; n < 4; n++) {
                m0 = fmaxf(m0, fmaxf(sv[n][0], sv[n][1]));
                m1 = fmaxf(m1, fmaxf(sv[n][2], sv[n][3]));
            }
            m0 = fmaxf(m0, __shfl_xor_sync(0xffffffffu, m0, 1));
            m0 = fmaxf(m0, __shfl_xor_sync(0xffffffffu, m0, 2));
            m1 = fmaxf(m1, __shfl_xor_sync(0xffffffffu, m1, 1));
            m1 = fmaxf(m1, __shfl_xor_sync(0xffffffffu, m1, 2));
            const float nm0 = fmaxf(mx0, m0);
            const float nm1 = fmaxf(mx1, m1);
            const float sc0 = __expf(mx0 - nm0);
            const float sc1 = __expf(mx1 - nm1);
            mx0 = nm0; mx1 = nm1;

            float e[4][4];
            float s0 = 0.f, s1 = 0.f;
#pragma unroll
            for (int n = 0; n < 4; n++) {
                e[n][0] = __expf(sv[n][0] - nm0);
                e[n][1] = __expf(sv[n][1] - nm0);
                e[n][2] = __expf(sv[n][2] - nm1);
                e[n][3] = __expf(sv[n][3] - nm1);
                s0 += e[n][0] + e[n][1];
                s1 += e[n][2] + e[n][3];
            }
            s0 += __shfl_xor_sync(0xffffffffu, s0, 1);
            s0 += __shfl_xor_sync(0xffffffffu, s0, 2);
            s1 += __shfl_xor_sync(0xffffffffu, s1, 1);
            s1 += __shfl_xor_sync(0xffffffffu, s1, 2);
            ls0 = ls0 * sc0 + s0;
            ls1 = ls1 * sc1 + s1;

#pragma unroll
            for (int dt = 0; dt < 8; dt++) {
                oa[dt][0] *= sc0; oa[dt][1] *= sc0;
                oa[dt][2] *= sc1; oa[dt][3] *= sc1;
            }
#pragma unroll
            for (int kk = 0; kk < 2; kk++) {
                pA[kk][0] = h2u(__floats2half2_rn(e[2 * kk][0], e[2 * kk][1]));
                pA[kk][1] = h2u(__floats2half2_rn(e[2 * kk][2], e[2 * kk][3]));
                pA[kk][2] = h2u(__floats2half2_rn(e[2 * kk + 1][0], e[2 * kk + 1][1]));
                pA[kk][3] = h2u(__floats2half2_rn(e[2 * kk + 1][2], e[2 * kk + 1][3]));
            }
        }

        // ---- O += P @ V  (B-fragments via ldmatrix.trans on row-major V) ----
#pragma unroll
        for (int kk = 0; kk < 2; kk++) {
            uint32_t bV[8][2];
#pragma unroll
            for (int g = 0; g < 4; g++) {
                uint32_t addr = vBase +
                    (uint32_t)(((key0 + kk * 16 + vRow) * LDV + g * 16 + vCol) * 2);
                uint32_t r[4];
                LDMX4T(r, addr);
                bV[2 * g][0] = r[0]; bV[2 * g][1] = r[1];
                bV[2 * g + 1][0] = r[2]; bV[2 * g + 1][1] = r[3];
            }
#pragma unroll
            for (int dt = 0; dt < 8; dt++)
                MMA16816(oa[dt], pA[kk], bV[dt]);
        }
    }

    // ---- store: ReLU(o / l) -> g_Oh ----
    {
        const float i0 = 1.0f / ls0;
        const float i1 = 1.0f / ls1;
        const int r = wq0 + (lane >> 2);
        const bool ok0 = r < S;
        const bool ok1 = (r + 8) < S;
#pragma unroll
        for (int dt = 0; dt < 8; dt++) {
            const int c = h * DH + dt * 8 + (lane & 3) * 2;
            if (ok0)
                *(__half2*)(g_Oh + (size_t)(start + r) * HID + c) =
                    __floats2half2_rn(fmaxf(oa[dt][0] * i0, 0.f),
                                      fmaxf(oa[dt][1] * i0, 0.f));
            if (ok1)
                *(__half2*)(g_Oh + (size_t)(start + r + 8) * HID + c) =
                    __floats2half2_rn(fmaxf(oa[dt][2] * i1, 0.f),
                                      fmaxf(oa[dt][3] * i1, 0.f));
        }
    }
}

// ============== Output projection + fused LayerNorm =========================
// 512 threads, 16 warps (4m x 4n), warp tile 32x64, BN=256 (full row / CTA).
// Both 128-K chunks double-buffered via cp.async (prefetched in prologue).
#define LDA 136
#define ST_HALVES ((128 + 256) * LDA)
#define PROJ_SMEM (2 * ST_HALVES * 2 + 4 * 128 * 2 * 4)

__global__ void __launch_bounds__(512, 1)
proj_ln_kernel(const float* __restrict__ bo,
               const float* __restrict__ gamma,
               const float* __restrict__ beta,
               float* __restrict__ out,
               int total) {
    extern __shared__ __half sh[];
    float* rsum = (float*)(sh + 2 * ST_HALVES);   // [4][128]
    float* rsq  = rsum + 4 * 128;                 // [4][128]

    const int row0 = blockIdx.x * 128;
    const int tid = threadIdx.x;
    const int lane = tid & 31;
    const int wid = tid >> 5;
    const __half* __restrict__ Wo16 = g_Wh + 3 * HID * HID;

    float acc[2][8][4];
#pragma unroll
    for (int f = 0; f < 2; f++)
#pragma unroll
        for (int j = 0; j < 8; j++)
#pragma unroll
            for (int e = 0; e < 4; e++) acc[f][j][e] = 0.f;

    const uint32_t sBase = smem_u32(sh);
    // A staging: thread -> row tid>>2, seg tid&3 (32 halves = 4 x 16B)
    const int arow = tid >> 2, aseg = tid & 3;
    const uint32_t aD = (uint32_t)((arow * LDA + aseg * 32) * 2);
    const __half* srcA = g_Oh + (size_t)(row0 + arow) * HID + aseg * 32;
    // B staging: thread -> row tid>>1, seg tid&1 (64 halves = 8 x 16B)
    const int brow = tid >> 1, bseg = tid & 1;
    const uint32_t bD = (uint32_t)((brow * LDA + bseg * 64) * 2) + 128 * LDA * 2;
    const __half* srcB = Wo16 + (size_t)brow * HID + bseg * 64;

    const int warp_m = (wid >> 2) * 32;
    const int warp_n = (wid & 3) * 64;
    const uint32_t aOff = (uint32_t)(((lane & 15) * LDA + (lane >> 4) * 8) * 2);
    const uint32_t bRow = (uint32_t)(((lane >> 4) << 3) + (lane & 7));
    const uint32_t bCol = (uint32_t)(((lane >> 3) & 1) * 8);

    // prologue: prefetch BOTH chunks (stages 0 and 1)
#pragma unroll
    for (int c = 0; c < 2; c++) {
        const uint32_t st = sBase + (uint32_t)(c * ST_HALVES * 2);
#pragma unroll
        for (int j = 0; j < 4; j++)
            CP16(st + aD + j * 16, srcA + c * 128 + j * 8);
#pragma unroll
        for (int j = 0; j < 8; j++)
            CP16(st + bD + j * 16, srcB + c * 128 + j * 8);
        CP_COMMIT;
    }

#pragma unroll
    for (int kc = 0; kc < 2; kc++) {
        if (kc == 0) CP_WAIT(1); else CP_WAIT(0);
        __syncthreads();

        const uint32_t aBase = sBase + (uint32_t)(kc * ST_HALVES * 2);
        const uint32_t bBase = aBase + 128 * LDA * 2;

#pragma unroll
        for (int ks = 0; ks < 8; ks++) {
            uint32_t a[2][4];
            uint32_t b[8][2];
#pragma unroll
            for (int f = 0; f < 2; f++) {
                uint32_t addr = aBase +
                    (uint32_t)(((warp_m + f * 16) * LDA + ks * 16) * 2) + aOff;
                LDMX4(a[f], addr);
            }
#pragma unroll
            for (int g = 0; g < 4; g++) {
                uint32_t addr = bBase +
                    (uint32_t)(((warp_n + g * 16 + bRow) * LDA +
                                ks * 16 + bCol) * 2);
                uint32_t r[4];
                LDMX4(r, addr);
                b[2 * g][0] = r[0]; b[2 * g][1] = r[1];
                b[2 * g + 1][0] = r[2]; b[2 * g + 1][1] = r[3];
            }
#pragma unroll
            for (int f = 0; f < 2; f++)
#pragma unroll
                for (int j = 0; j < 8; j++)
                    MMA16816(acc[f][j], a[f], b[j]);
        }
    }

    // ---- bias add + per-row partial sums ----
#pragma unroll
    for (int f = 0; f < 2; f++) {
        float sl = 0.f, ql = 0.f, shg = 0.f, qh = 0.f;
#pragma unroll
        for (int j = 0; j < 8; j++) {
            const int col = warp_n + j * 8 + (lane & 3) * 2;
            float2 bb = *(const float2*)(bo + col);
            acc[f][j][0] += bb.x; acc[f][j][1] += bb.y;
            acc[f][j][2] += bb.x; acc[f][j][3] += bb.y;
            sl += acc[f][j][0] + acc[f][j][1];
            ql += acc[f][j][0] * acc[f][j][0] + acc[f][j][1] * acc[f][j][1];
            shg += acc[f][j][2] + acc[f][j][3];
            qh += acc[f][j][2] * acc[f][j][2] + acc[f][j][3] * acc[f][j][3];
        }
        sl += __shfl_xor_sync(0xffffffffu, sl, 1);
        sl += __shfl_xor_sync(0xffffffffu, sl, 2);
        ql += __shfl_xor_sync(0xffffffffu, ql, 1);
        ql += __shfl_xor_sync(0xffffffffu, ql, 2);
        shg += __shfl_xor_sync(0xffffffffu, shg, 1);
        shg += __shfl_xor_sync(0xffffffffu, shg, 2);
        qh += __shfl_xor_sync(0xffffffffu, qh, 1);
        qh += __shfl_xor_sync(0xffffffffu, qh, 2);
        if ((lane & 3) == 0) {
            const int nw = wid & 3;
            const int rlo = warp_m + f * 16 + (lane >> 2);
            rsum[nw * 128 + rlo] = sl;
            rsq[nw * 128 + rlo] = ql;
            rsum[nw * 128 + rlo + 8] = shg;
            rsq[nw * 128 + rlo + 8] = qh;
        }
    }
    __syncthreads();

    // ---- LN + store ----
#pragma unroll
    for (int f = 0; f < 2; f++) {
        const int rlo = warp_m + f * 16 + (lane >> 2);
        const int rhi = rlo + 8;
        float s0 = rsum[rlo] + rsum[128 + rlo] + rsum[256 + rlo] + rsum[384 + rlo];
        float q0 = rsq[rlo] + rsq[128 + rlo] + rsq[256 + rlo] + rsq[384 + rlo];
        float s1 = rsum[rhi] + rsum[128 + rhi] + rsum[256 + rhi] + rsum[384 + rhi];
        float q1 = rsq[rhi] + rsq[128 + rhi] + rsq[256 + rhi] + rsq[384 + rhi];
        const float mu0 = s0 * (1.f / 256.f);
        const float mu1 = s1 * (1.f / 256.f);
        const float rs0 = rsqrtf(fmaxf(q0 * (1.f / 256.f) - mu0 * mu0, 0.f) + 1e-5f);
        const float rs1 = rsqrtf(fmaxf(q1 * (1.f / 256.f) - mu1 * mu1, 0.f) + 1e-5f);
        const int g_lo = row0 + rlo;
        const int g_hi = row0 + rhi;
        const bool ok0 = g_lo < total;
        const bool ok1 = g_hi < total;
        const bool z0 = (g_lo == 0);
#pragma unroll
        for (int j = 0; j < 8; j++) {
            const int col = warp_n + j * 8 + (lane & 3) * 2;
            float2 gg = *(const float2*)(gamma + col);
            float2 be = *(const float2*)(beta + col);
            if (ok0) {
                float2 v;
                if (z0) { v.x = 0.f; v.y = 0.f; }
                else {
                    v.x = (acc[f][j][0] - mu0) * rs0 * gg.x + be.x;
                    v.y = (acc[f][j][1] - mu0) * rs0 * gg.y + be.y;
                }
                *(float2*)(out + (size_t)g_lo * HID + col) = v;
            }
            if (ok1) {
                float2 v;
                v.x = (acc[f][j][2] - mu1) * rs1 * gg.x + be.x;
                v.y = (acc[f][j][3] - mu1) * rs1 * gg.y + be.y;
                *(float2*)(out + (size_t)g_hi * HID + col) = v;
            }
        }
    }
}

// ---------------------------------------------------------------------------
extern "C" void kernel_launch(void* const* d_in, const int* in_sizes, int n_in,
                              void* d_out, int out_size) {
    const float* msg      = (const float*)d_in[0];
    const float* Wq       = (const float*)d_in[1];
    const float* Wk       = (const float*)d_in[2];
    const float* Wv       = (const float*)d_in[3];
    const float* Wo       = (const float*)d_in[4];
    const float* bo       = (const float*)d_in[5];
    const float* gamma    = (const float*)d_in[6];
    const float* beta     = (const float*)d_in[7];
    const int*   b_starts = (const int*)d_in[8];
    const int*   b_sizes  = (const int*)d_in[9];
    float* out = (float*)d_out;

    const int total = in_sizes[0] / HID;
    const int tiles = (total + 127) / 128;

    cudaFuncSetAttribute(qkv_mma_kernel,
                         cudaFuncAttributeMaxDynamicSharedMemorySize, GEMM_SMEM);
    cudaFuncSetAttribute(attn_mma_kernel,
                         cudaFuncAttributeMaxDynamicSharedMemorySize, ATTN_SMEM);
    cudaFuncSetAttribute(proj_ln_kernel,
                         cudaFuncAttributeMaxDynamicSharedMemorySize, PROJ_SMEM);

    cvt_msg_kernel<<<(total * (HID / 8) + 511) / 512, 512>>>(msg, total);
    cvt_w_kernel<<<128, 256>>>(Wq, Wk, Wv, Wo);

    dim3 ga(6, tiles);
    qkv_mma_kernel<<<ga, 256, GEMM_SMEM>>>(total);

    dim3 gb(N_MOLS, NH);
    attn_mma_kernel<<<gb, 256, ATTN_SMEM>>>(b_starts, b_sizes);

    proj_ln_kernel<<<tiles, 512, PROJ_SMEM>>>(bo, gamma, beta, out, total);
}

// round 16
// speedup vs baseline: 1.0241x; 1.0237x over previous
#include <cuda_runtime.h>
#include <cuda_fp16.h>
#include <cstdint>

#define HID 256
#define NH 4
#define DH 64
#define N_MOLS 2048
#define MAX_LEN 128
#define MAX_TOTAL (1 + N_MOLS * MAX_LEN)

// Scratch (device globals: allocation-free rule). Zero-initialized at load.
__device__ unsigned short g_Xh_u[(size_t)MAX_TOTAL * HID];   // msg fp16
__device__ unsigned short g_Qh_u[(size_t)MAX_TOTAL * HID];
__device__ unsigned short g_Kh_u[(size_t)MAX_TOTAL * HID];
__device__ unsigned short g_Vh_u[(size_t)MAX_TOTAL * HID];
__device__ unsigned short g_Oh_u[(size_t)MAX_TOTAL * HID];
__device__ unsigned short g_Wh_u[4 * HID * HID];             // Wq,Wk,Wv,Wo fp16

#define g_Xh ((__half*)g_Xh_u)
#define g_Qh ((__half*)g_Qh_u)
#define g_Kh ((__half*)g_Kh_u)
#define g_Vh ((__half*)g_Vh_u)
#define g_Oh ((__half*)g_Oh_u)
#define g_Wh ((__half*)g_Wh_u)

// ============================ helpers =======================================
__device__ __forceinline__ uint32_t smem_u32(const void* p) {
    uint32_t a;
    asm("{ .reg .u64 t; cvta.to.shared.u64 t, %1; cvt.u32.u64 %0, t; }"
        : "=r"(a) : "l"(p));
    return a;
}
__device__ __forceinline__ uint32_t h2u(__half2 h) {
    return *reinterpret_cast<uint32_t*>(&h);
}
__device__ __forceinline__ uint4 cvt8(float4 v0, float4 v1) {
    uint4 w;
    w.x = h2u(__floats2half2_rn(v0.x, v0.y));
    w.y = h2u(__floats2half2_rn(v0.z, v0.w));
    w.z = h2u(__floats2half2_rn(v1.x, v1.y));
    w.w = h2u(__floats2half2_rn(v1.z, v1.w));
    return w;
}

#define CP16(dst, src) \
    asm volatile("cp.async.cg.shared.global [%0], [%1], 16;" \
                 :: "r"(dst), "l"(src) : "memory")
#define CP_COMMIT \
    asm volatile("cp.async.commit_group;" ::: "memory")
#define CP_WAIT(n) \
    asm volatile("cp.async.wait_group %0;" :: "n"(n) : "memory")

#define LDMX4(r, addr) \
    asm volatile("ldmatrix.sync.aligned.m8n8.x4.shared.b16 {%0,%1,%2,%3}, [%4];" \
                 : "=r"((r)[0]), "=r"((r)[1]), "=r"((r)[2]), "=r"((r)[3]) \
                 : "r"(addr))

#define LDMX4T(r, addr) \
    asm volatile("ldmatrix.sync.aligned.m8n8.x4.trans.shared.b16 {%0,%1,%2,%3}, [%4];" \
                 : "=r"((r)[0]), "=r"((r)[1]), "=r"((r)[2]), "=r"((r)[3]) \
                 : "r"(addr))

#define MMA16816(d, a, b) \
    asm volatile("mma.sync.aligned.m16n8k16.row.col.f32.f16.f16.f32 " \
                 "{%0,%1,%2,%3}, {%4,%5,%6,%7}, {%8,%9}, {%0,%1,%2,%3};" \
                 : "+f"((d)[0]), "+f"((d)[1]), "+f"((d)[2]), "+f"((d)[3]) \
                 : "r"((a)[0]), "r"((a)[1]), "r"((a)[2]), "r"((a)[3]), \
                   "r"((b)[0]), "r"((b)[1]))

// ======================= conversion kernels =================================
__global__ void __launch_bounds__(512)
cvt_msg_kernel(const float* __restrict__ msg, int total) {
    const int idx = blockIdx.x * 512 + threadIdx.x;   // one per 8 floats
    const int n = total * (HID / 8);
    if (idx >= n) return;
    const float4* p = (const float4*)msg + (size_t)idx * 2;
    ((uint4*)g_Xh)[idx] = cvt8(p[0], p[1]);
}

__global__ void __launch_bounds__(256)
cvt_w_kernel(const float* __restrict__ Wq, const float* __restrict__ Wk,
             const float* __restrict__ Wv, const float* __restrict__ Wo) {
    const int idx = blockIdx.x * 256 + threadIdx.x;   // 4*8192 groups of 8
    const int mat = idx >> 13;
    const int off = idx & 8191;
    const float* W = (mat == 0) ? Wq : (mat == 1 ? Wk : (mat == 2 ? Wv : Wo));
    const float4* p = (const float4*)W + (size_t)off * 2;
    ((uint4*)(g_Wh + mat * HID * HID))[off] = cvt8(p[0], p[1]);
}

// ======================= QKV GEMM (fp16 in, fp16 out) =======================
// Out[r][c] = sum_k X[r][k] * W[c][k]; 128x128 tile, 256 thr, warp 64x32.
// BK=64, 4 chunks, double-buffered cp.async (2 stages x (A+B) 72-stride).
#define LDC 72
#define CHUNK_HALVES (128 * LDC)
#define GEMM_SMEM (4 * CHUNK_HALVES * 2)   // 73728 B

__global__ void __launch_bounds__(256, 2)
qkv_mma_kernel(int total) {
    extern __shared__ __half sh[];

    const int bx = blockIdx.x;            // 0..5 fastest -> X-tile L2 reuse
    const int mat = bx >> 1;
    const int c0 = (bx & 1) * 128;
    const __half* __restrict__ Ah = g_Xh;
    const __half* __restrict__ Wh = g_Wh + mat * HID * HID;
    __half* __restrict__ OutH = (mat == 0) ? g_Qh : (mat == 1 ? g_Kh : g_Vh);
    const int row0 = blockIdx.y * 128;

    const int tid = threadIdx.x;
    const int lane = tid & 31;
    const int wid = tid >> 5;

    float acc[4][4][4];
#pragma unroll
    for (int f = 0; f < 4; f++)
#pragma unroll
        for (int j = 0; j < 4; j++)
#pragma unroll
            for (int e = 0; e < 4; e++) acc[f][j][e] = 0.f;

    const int srow = tid >> 1;            // 0..127
    const int sseg = (tid & 1) * 32;      // 32-half segment of the 64-chunk
    const uint32_t base0 = smem_u32(sh);
    const uint32_t stageA0 = base0;
    const uint32_t stageA1 = base0 + CHUNK_HALVES * 2;
    const uint32_t stageB0 = base0 + 2 * CHUNK_HALVES * 2;
    const uint32_t stageB1 = base0 + 3 * CHUNK_HALVES * 2;
    const uint32_t dOffs = (uint32_t)((srow * LDC + sseg) * 2);
    const __half* srcA = Ah + (size_t)(row0 + srow) * HID + sseg;
    const __half* srcB = Wh + (size_t)(c0 + srow) * HID + sseg;

    const int warp_m = (wid >> 2) * 64;
    const int warp_n = (wid & 3) * 32;
    const uint32_t aOff = (uint32_t)(((lane & 15) * LDC + (lane >> 4) * 8) * 2);
    const uint32_t bRow = (uint32_t)(((lane >> 4) << 3) + (lane & 7));
    const uint32_t bCol = (uint32_t)(((lane >> 3) & 1) * 8);

    // prologue: prefetch chunks 0 and 1
#pragma unroll
    for (int c = 0; c < 2; c++) {
        const uint32_t dA = (c == 0 ? stageA0 : stageA1) + dOffs;
        const uint32_t dB = (c == 0 ? stageB0 : stageB1) + dOffs;
#pragma unroll
        for (int j = 0; j < 4; j++) {     // 32 halves = 4 x 16B
            CP16(dA + j * 16, srcA + c * 64 + j * 8);
            CP16(dB + j * 16, srcB + c * 64 + j * 8);
        }
        CP_COMMIT;
    }

#pragma unroll
    for (int c = 0; c < 4; c++) {
        if (c < 3) CP_WAIT(1); else CP_WAIT(0);
        __syncthreads();

        const uint32_t aB = (c & 1) ? stageA1 : stageA0;
        const uint32_t bB = (c & 1) ? stageB1 : stageB0;

#pragma unroll
        for (int ks = 0; ks < 4; ks++) {
            uint32_t a[4][4];
            uint32_t b[4][2];
#pragma unroll
            for (int f = 0; f < 4; f++) {
                uint32_t addr = aB +
                    (uint32_t)(((warp_m + f * 16) * LDC + ks * 16) * 2) + aOff;
                LDMX4(a[f], addr);
            }
#pragma unroll
            for (int g = 0; g < 2; g++) {
                uint32_t addr = bB +
                    (uint32_t)(((warp_n + g * 16 + bRow) * LDC +
                                ks * 16 + bCol) * 2);
                uint32_t r[4];
                LDMX4(r, addr);
                b[2 * g][0] = r[0]; b[2 * g][1] = r[1];
                b[2 * g + 1][0] = r[2]; b[2 * g + 1][1] = r[3];
            }
#pragma unroll
            for (int f = 0; f < 4; f++)
#pragma unroll
                for (int j = 0; j < 4; j++)
                    MMA16816(acc[f][j], a[f], b[j]);
        }
        __syncthreads();

        if (c + 2 < 4) {
            const uint32_t dA = ((c & 1) ? stageA1 : stageA0) + dOffs;
            const uint32_t dB = ((c & 1) ? stageB1 : stageB0) + dOffs;
#pragma unroll
            for (int j = 0; j < 4; j++) {
                CP16(dA + j * 16, srcA + (c + 2) * 64 + j * 8);
                CP16(dB + j * 16, srcB + (c + 2) * 64 + j * 8);
            }
            CP_COMMIT;
        }
    }

#pragma unroll
    for (int f = 0; f < 4; f++) {
        const int row_lo = row0 + warp_m + f * 16 + (lane >> 2);
        const int row_hi = row_lo + 8;
#pragma unroll
        for (int j = 0; j < 4; j++) {
            const int col = c0 + warp_n + j * 8 + (lane & 3) * 2;
            if (row_lo < total)
                *(__half2*)(OutH + (size_t)row_lo * HID + col) =
                    __floats2half2_rn(acc[f][j][0], acc[f][j][1]);
            if (row_hi < total)
                *(__half2*)(OutH + (size_t)row_hi * HID + col) =
                    __floats2half2_rn(acc[f][j][2], acc[f][j][3]);
        }
    }
}

// ================ Flash attention (HMMA, online softmax) ====================
// CTA = (mol, head); 8 warps x 16 query rows; 32-key chunks.
// Staging: guarded LDG+STS (measured fastest: L1 row reuse across head CTAs).
#define LDQ 72
#define LDK 72
#define LDV 72
#define ATTN_SMEM (3 * 128 * LDQ * 2)

__global__ void __launch_bounds__(256, 3)
attn_mma_kernel(const int* __restrict__ b_starts,
                const int* __restrict__ b_sizes) {
    extern __shared__ __half ash[];
    __half* qS = ash;
    __half* kS = ash + 128 * LDQ;
    __half* vS = ash + 2 * 128 * LDQ;

    const int m = blockIdx.x;
    const int h = blockIdx.y;
    const int S = b_sizes[m];
    const int start = b_starts[m];
    const int tid = threadIdx.x;
    const int lane = tid & 31;
    const int wid = tid >> 5;          // 0..7

    // ---- stage Q, K, V row-major (zero beyond S) ----
    {
        const int tok = tid >> 1;
        const int seg = (tid & 1) * 32;
        const bool ok = tok < S;
        const __half* qp = g_Qh + (size_t)(start + tok) * HID + h * DH + seg;
        const __half* kp = g_Kh + (size_t)(start + tok) * HID + h * DH + seg;
        const __half* vp = g_Vh + (size_t)(start + tok) * HID + h * DH + seg;
        const uint4 z = make_uint4(0, 0, 0, 0);
#pragma unroll
        for (int j = 0; j < 4; j++) {       // 32 halves = 4 x uint4
            uint4 qv = ok ? ((const uint4*)qp)[j] : z;
            uint4 kv = ok ? ((const uint4*)kp)[j] : z;
            uint4 vv = ok ? ((const uint4*)vp)[j] : z;
            *(uint4*)(qS + tok * LDQ + seg + j * 8) = qv;
            *(uint4*)(kS + tok * LDK + seg + j * 8) = kv;
            *(uint4*)(vS + tok * LDV + seg + j * 8) = vv;
        }
    }
    __syncthreads();

    const int wq0 = wid * 16;
    if (wq0 >= S) return;   // idle query warps exit (no more barriers below)

    const uint32_t qBase = smem_u32(qS);
    const uint32_t kBase = smem_u32(kS);
    const uint32_t vBase = smem_u32(vS);
    const uint32_t aOff = (uint32_t)(((lane & 15) * LDQ + (lane >> 4) * 8) * 2);
    const uint32_t bRow = (uint32_t)(((lane >> 4) << 3) + (lane & 7));
    const uint32_t bCol = (uint32_t)(((lane >> 3) & 1) * 8);
    // trans-load lane map for V: k-row and n(d)-offset
    const uint32_t vRow = (uint32_t)((lane & 7) + ((lane >> 3) & 1) * 8);
    const uint32_t vCol = (uint32_t)((lane >> 4) * 8);

    float oa[8][4];
#pragma unroll
    for (int dt = 0; dt < 8; dt++)
#pragma unroll
        for (int e = 0; e < 4; e++) oa[dt][e] = 0.f;
    float mx0 = -3.0e38f, mx1 = -3.0e38f;
    float ls0 = 0.f, ls1 = 0.f;

    const int nchunks = (S + 31) >> 5;
    for (int ch = 0; ch < nchunks; ch++) {
        const int key0 = ch * 32;

        float sacc[4][4];
#pragma unroll
        for (int n = 0; n < 4; n++)
#pragma unroll
            for (int e = 0; e < 4; e++) sacc[n][e] = 0.f;

#pragma unroll
        for (int kd = 0; kd < 4; kd++) {
            uint32_t qA[4];
            {
                uint32_t addr = qBase +
                    (uint32_t)((wq0 * LDQ + kd * 16) * 2) + aOff;
                LDMX4(qA, addr);
            }
            uint32_t bK[4][2];
#pragma unroll
            for (int g = 0; g < 2; g++) {
                uint32_t addr = kBase +
                    (uint32_t)(((key0 + g * 16 + bRow) * LDK + kd * 16 + bCol) * 2);
                uint32_t r[4];
                LDMX4(r, addr);
                bK[2 * g][0] = r[0]; bK[2 * g][1] = r[1];
                bK[2 * g + 1][0] = r[2]; bK[2 * g + 1][1] = r[3];
            }
#pragma unroll
            for (int n = 0; n < 4; n++)
                MMA16816(sacc[n], qA, bK[n]);
        }

        // ---- online softmax (rows lane>>2 and +8 of this 16-row block) ----
        uint32_t pA[2][4];
        {
            float sv[4][4];
#pragma unroll
            for (int n = 0; n < 4; n++) {
                const int cb = key0 + n * 8 + (lane & 3) * 2;
                const bool k0ok = cb < S;
                const bool k1ok = (cb + 1) < S;
                sv[n][0] = k0ok ? sacc[n][0] * 0.125f : -1.0e30f;
                sv[n][1] = k1ok ? sacc[n][1] * 0.125f : -1.0e30f;
                sv[n][2] = k0ok ? sacc[n][2] * 0.125f : -1.0e30f;
                sv[n][3] = k1ok ? sacc[n][3] * 0.125f : -1.0e30f;
            }
            float m0 = -3.0e38f, m1 = -3.0e38f;
#pragma unroll
            for (int n = 0; n < 4; n++) {
                m0 = fmaxf(m0, fmaxf(sv[n][0], sv[n][1]));
                m1 = fmaxf(m1, fmaxf(sv[n][2], sv[n][3]));
            }
            m0 = fmaxf(m0, __shfl_xor_sync(0xffffffffu, m0, 1));
            m0 = fmaxf(m0, __shfl_xor_sync(0xffffffffu, m0, 2));
            m1 = fmaxf(m1, __shfl_xor_sync(0xffffffffu, m1, 1));
            m1 = fmaxf(m1, __shfl_xor_sync(0xffffffffu, m1, 2));
            const float nm0 = fmaxf(mx0, m0);
            const float nm1 = fmaxf(mx1, m1);
            const float sc0 = __expf(mx0 - nm0);
            const float sc1 = __expf(mx1 - nm1);
            mx0 = nm0; mx1 = nm1;

            float e[4][4];
            float s0 = 0.f, s1 = 0.f;
#pragma unroll
            for (int n = 0; n < 4; n++) {
                e[n][0] = __expf(sv[n][0] - nm0);
                e[n][1] = __expf(sv[n][1] - nm0);
                e[n][2] = __expf(sv[n][2] - nm1);
                e[n][3] = __expf(sv[n][3] - nm1);
                s0 += e[n][0] + e[n][1];
                s1 += e[n][2] + e[n][3];
            }
            s0 += __shfl_xor_sync(0xffffffffu, s0, 1);
            s0 += __shfl_xor_sync(0xffffffffu, s0, 2);
            s1 += __shfl_xor_sync(0xffffffffu, s1, 1);
            s1 += __shfl_xor_sync(0xffffffffu, s1, 2);
            ls0 = ls0 * sc0 + s0;
            ls1 = ls1 * sc1 + s1;

#pragma unroll
            for (int dt = 0; dt < 8; dt++) {
                oa[dt][0] *= sc0; oa[dt][1] *= sc0;
                oa[dt][2] *= sc1; oa[dt][3] *= sc1;
            }
#pragma unroll
            for (int kk = 0; kk < 2; kk++) {
                pA[kk][0] = h2u(__floats2half2_rn(e[2 * kk][0], e[2 * kk][1]));
                pA[kk][1] = h2u(__floats2half2_rn(e[2 * kk][2], e[2 * kk][3]));
                pA[kk][2] = h2u(__floats2half2_rn(e[2 * kk + 1][0], e[2 * kk + 1][1]));
                pA[kk][3] = h2u(__floats2half2_rn(e[2 * kk + 1][2], e[2 * kk + 1][3]));
            }
        }

        // ---- O += P @ V  (B-fragments via ldmatrix.trans on row-major V) ----
#pragma unroll
        for (int kk = 0; kk < 2; kk++) {
            uint32_t bV[8][2];
#pragma unroll
            for (int g = 0; g < 4; g++) {
                uint32_t addr = vBase +
                    (uint32_t)(((key0 + kk * 16 + vRow) * LDV + g * 16 + vCol) * 2);
                uint32_t r[4];
                LDMX4T(r, addr);
                bV[2 * g][0] = r[0]; bV[2 * g][1] = r[1];
                bV[2 * g + 1][0] = r[2]; bV[2 * g + 1][1] = r[3];
            }
#pragma unroll
            for (int dt = 0; dt < 8; dt++)
                MMA16816(oa[dt], pA[kk], bV[dt]);
        }
    }

    // ---- store: ReLU(o / l) -> g_Oh ----
    {
        const float i0 = 1.0f / ls0;
        const float i1 = 1.0f / ls1;
        const int r = wq0 + (lane >> 2);
        const bool ok0 = r < S;
        const bool ok1 = (r + 8) < S;
#pragma unroll
        for (int dt = 0; dt < 8; dt++) {
            const int c = h * DH + dt * 8 + (lane & 3) * 2;
            if (ok0)
                *(__half2*)(g_Oh + (size_t)(start + r) * HID + c) =
                    __floats2half2_rn(fmaxf(oa[dt][0] * i0, 0.f),
                                      fmaxf(oa[dt][1] * i0, 0.f));
            if (ok1)
                *(__half2*)(g_Oh + (size_t)(start + r + 8) * HID + c) =
                    __floats2half2_rn(fmaxf(oa[dt][2] * i1, 0.f),
                                      fmaxf(oa[dt][3] * i1, 0.f));
        }
    }
}

// ============== Output projection + fused LayerNorm =========================
// 512 threads, 16 warps (4m x 4n), warp tile 32x64, BN=256 (full row / CTA).
// Both 128-K chunks double-buffered via cp.async (prefetched in prologue).
#define LDA 136
#define ST_HALVES ((128 + 256) * LDA)
#define PROJ_SMEM (2 * ST_HALVES * 2 + 4 * 128 * 2 * 4)

__global__ void __launch_bounds__(512, 1)
proj_ln_kernel(const float* __restrict__ bo,
               const float* __restrict__ gamma,
               const float* __restrict__ beta,
               float* __restrict__ out,
               int total) {
    extern __shared__ __half sh[];
    float* rsum = (float*)(sh + 2 * ST_HALVES);   // [4][128]
    float* rsq  = rsum + 4 * 128;                 // [4][128]

    const int row0 = blockIdx.x * 128;
    const int tid = threadIdx.x;
    const int lane = tid & 31;
    const int wid = tid >> 5;
    const __half* __restrict__ Wo16 = g_Wh + 3 * HID * HID;

    float acc[2][8][4];
#pragma unroll
    for (int f = 0; f < 2; f++)
#pragma unroll
        for (int j = 0; j < 8; j++)
#pragma unroll
            for (int e = 0; e < 4; e++) acc[f][j][e] = 0.f;

    const uint32_t sBase = smem_u32(sh);
    // A staging: thread -> row tid>>2, seg tid&3 (32 halves = 4 x 16B)
    const int arow = tid >> 2, aseg = tid & 3;
    const uint32_t aD = (uint32_t)((arow * LDA + aseg * 32) * 2);
    const __half* srcA = g_Oh + (size_t)(row0 + arow) * HID + aseg * 32;
    // B staging: thread -> row tid>>1, seg tid&1 (64 halves = 8 x 16B)
    const int brow = tid >> 1, bseg = tid & 1;
    const uint32_t bD = (uint32_t)((brow * LDA + bseg * 64) * 2) + 128 * LDA * 2;
    const __half* srcB = Wo16 + (size_t)brow * HID + bseg * 64;

    const int warp_m = (wid >> 2) * 32;
    const int warp_n = (wid & 3) * 64;
    const uint32_t aOff = (uint32_t)(((lane & 15) * LDA + (lane >> 4) * 8) * 2);
    const uint32_t bRow = (uint32_t)(((lane >> 4) << 3) + (lane & 7));
    const uint32_t bCol = (uint32_t)(((lane >> 3) & 1) * 8);

    // prologue: prefetch BOTH chunks (stages 0 and 1)
#pragma unroll
    for (int c = 0; c < 2; c++) {
        const uint32_t st = sBase + (uint32_t)(c * ST_HALVES * 2);
#pragma unroll
        for (int j = 0; j < 4; j++)
            CP16(st + aD + j * 16, srcA + c * 128 + j * 8);
#pragma unroll
        for (int j = 0; j < 8; j++)
            CP16(st + bD + j * 16, srcB + c * 128 + j * 8);
        CP_COMMIT;
    }

#pragma unroll
    for (int kc = 0; kc < 2; kc++) {
        if (kc == 0) CP_WAIT(1); else CP_WAIT(0);
        __syncthreads();

        const uint32_t aBase = sBase + (uint32_t)(kc * ST_HALVES * 2);
        const uint32_t bBase = aBase + 128 * LDA * 2;

#pragma unroll
        for (int ks = 0; ks < 8; ks++) {
            uint32_t a[2][4];
            uint32_t b[8][2];
#pragma unroll
            for (int f = 0; f < 2; f++) {
                uint32_t addr = aBase +
                    (uint32_t)(((warp_m + f * 16) * LDA + ks * 16) * 2) + aOff;
                LDMX4(a[f], addr);
            }
#pragma unroll
            for (int g = 0; g < 4; g++) {
                uint32_t addr = bBase +
                    (uint32_t)(((warp_n + g * 16 + bRow) * LDA +
                                ks * 16 + bCol) * 2);
                uint32_t r[4];
                LDMX4(r, addr);
                b[2 * g][0] = r[0]; b[2 * g][1] = r[1];
                b[2 * g + 1][0] = r[2]; b[2 * g + 1][1] = r[3];
            }
#pragma unroll
            for (int f = 0; f < 2; f++)
#pragma unroll
                for (int j = 0; j < 8; j++)
                    MMA16816(acc[f][j], a[f], b[j]);
        }
    }

    // ---- bias add + per-row partial sums ----
#pragma unroll
    for (int f = 0; f < 2; f++) {
        float sl = 0.f, ql = 0.f, shg = 0.f, qh = 0.f;
#pragma unroll
        for (int j = 0; j < 8; j++) {
            const int col = warp_n + j * 8 + (lane & 3) * 2;
            float2 bb = *(const float2*)(bo + col);
            acc[f][j][0] += bb.x; acc[f][j][1] += bb.y;
            acc[f][j][2] += bb.x; acc[f][j][3] += bb.y;
            sl += acc[f][j][0] + acc[f][j][1];
            ql += acc[f][j][0] * acc[f][j][0] + acc[f][j][1] * acc[f][j][1];
            shg += acc[f][j][2] + acc[f][j][3];
            qh += acc[f][j][2] * acc[f][j][2] + acc[f][j][3] * acc[f][j][3];
        }
        sl += __shfl_xor_sync(0xffffffffu, sl, 1);
        sl += __shfl_xor_sync(0xffffffffu, sl, 2);
        ql += __shfl_xor_sync(0xffffffffu, ql, 1);
        ql += __shfl_xor_sync(0xffffffffu, ql, 2);
        shg += __shfl_xor_sync(0xffffffffu, shg, 1);
        shg += __shfl_xor_sync(0xffffffffu, shg, 2);
        qh += __shfl_xor_sync(0xffffffffu, qh, 1);
        qh += __shfl_xor_sync(0xffffffffu, qh, 2);
        if ((lane & 3) == 0) {
            const int nw = wid & 3;
            const int rlo = warp_m + f * 16 + (lane >> 2);
            rsum[nw * 128 + rlo] = sl;
            rsq[nw * 128 + rlo] = ql;
            rsum[nw * 128 + rlo + 8] = shg;
            rsq[nw * 128 + rlo + 8] = qh;
        }
    }
    __syncthreads();

    // ---- LN + store ----
#pragma unroll
    for (int f = 0; f < 2; f++) {
        const int rlo = warp_m + f * 16 + (lane >> 2);
        const int rhi = rlo + 8;
        float s0 = rsum[rlo] + rsum[128 + rlo] + rsum[256 + rlo] + rsum[384 + rlo];
        float q0 = rsq[rlo] + rsq[128 + rlo] + rsq[256 + rlo] + rsq[384 + rlo];
        float s1 = rsum[rhi] + rsum[128 + rhi] + rsum[256 + rhi] + rsum[384 + rhi];
        float q1 = rsq[rhi] + rsq[128 + rhi] + rsq[256 + rhi] + rsq[384 + rhi];
        const float mu0 = s0 * (1.f / 256.f);
        const float mu1 = s1 * (1.f / 256.f);
        const float rs0 = rsqrtf(fmaxf(q0 * (1.f / 256.f) - mu0 * mu0, 0.f) + 1e-5f);
        const float rs1 = rsqrtf(fmaxf(q1 * (1.f / 256.f) - mu1 * mu1, 0.f) + 1e-5f);
        const int g_lo = row0 + rlo;
        const int g_hi = row0 + rhi;
        const bool ok0 = g_lo < total;
        const bool ok1 = g_hi < total;
        const bool z0 = (g_lo == 0);
#pragma unroll
        for (int j = 0; j < 8; j++) {
            const int col = warp_n + j * 8 + (lane & 3) * 2;
            float2 gg = *(const float2*)(gamma + col);
            float2 be = *(const float2*)(beta + col);
            if (ok0) {
                float2 v;
                if (z0) { v.x = 0.f; v.y = 0.f; }
                else {
                    v.x = (acc[f][j][0] - mu0) * rs0 * gg.x + be.x;
                    v.y = (acc[f][j][1] - mu0) * rs0 * gg.y + be.y;
                }
                *(float2*)(out + (size_t)g_lo * HID + col) = v;
            }
            if (ok1) {
                float2 v;
                v.x = (acc[f][j][2] - mu1) * rs1 * gg.x + be.x;
                v.y = (acc[f][j][3] - mu1) * rs1 * gg.y + be.y;
                *(float2*)(out + (size_t)g_hi * HID + col) = v;
            }
        }
    }
}

// ---------------------------------------------------------------------------
extern "C" void kernel_launch(void* const* d_in, const int* in_sizes, int n_in,
                              void* d_out, int out_size) {
    const float* msg      = (const float*)d_in[0];
    const float* Wq       = (const float*)d_in[1];
    const float* Wk       = (const float*)d_in[2];
    const float* Wv       = (const float*)d_in[3];
    const float* Wo       = (const float*)d_in[4];
    const float* bo       = (const float*)d_in[5];
    const float* gamma    = (const float*)d_in[6];
    const float* beta     = (const float*)d_in[7];
    const int*   b_starts = (const int*)d_in[8];
    const int*   b_sizes  = (const int*)d_in[9];
    float* out = (float*)d_out;

    const int total = in_sizes[0] / HID;
    const int tiles = (total + 127) / 128;

    cudaFuncSetAttribute(qkv_mma_kernel,
                         cudaFuncAttributeMaxDynamicSharedMemorySize, GEMM_SMEM);
    cudaFuncSetAttribute(attn_mma_kernel,
                         cudaFuncAttributeMaxDynamicSharedMemorySize, ATTN_SMEM);
    cudaFuncSetAttribute(proj_ln_kernel,
                         cudaFuncAttributeMaxDynamicSharedMemorySize, PROJ_SMEM);

    cvt_msg_kernel<<<(total * (HID / 8) + 511) / 512, 512>>>(msg, total);
    cvt_w_kernel<<<128, 256>>>(Wq, Wk, Wv, Wo);

    dim3 ga(6, tiles);
    qkv_mma_kernel<<<ga, 256, GEMM_SMEM>>>(total);

    dim3 gb(N_MOLS, NH);
    attn_mma_kernel<<<gb, 256, ATTN_SMEM>>>(b_starts, b_sizes);

    proj_ln_kernel<<<tiles, 512, PROJ_SMEM>>>(bo, gamma, beta, out, total);
}

// round 17
// speedup vs baseline: 1.0281x; 1.0039x over previous
#include <cuda_runtime.h>
#include <cuda_fp16.h>
#include <cstdint>

#define HID 256
#define NH 4
#define DH 64
#define N_MOLS 2048
#define MAX_LEN 128
#define MAX_TOTAL (1 + N_MOLS * MAX_LEN)

// Scratch (device globals: allocation-free rule). Zero-initialized at load.
__device__ unsigned short g_Xh_u[(size_t)MAX_TOTAL * HID];   // msg fp16
__device__ unsigned short g_Qh_u[(size_t)MAX_TOTAL * HID];
__device__ unsigned short g_Kh_u[(size_t)MAX_TOTAL * HID];
__device__ unsigned short g_Vh_u[(size_t)MAX_TOTAL * HID];
__device__ unsigned short g_Oh_u[(size_t)MAX_TOTAL * HID];
__device__ unsigned short g_Wh_u[4 * HID * HID];             // Wq,Wk,Wv,Wo fp16

#define g_Xh ((__half*)g_Xh_u)
#define g_Qh ((__half*)g_Qh_u)
#define g_Kh ((__half*)g_Kh_u)
#define g_Vh ((__half*)g_Vh_u)
#define g_Oh ((__half*)g_Oh_u)
#define g_Wh ((__half*)g_Wh_u)

// ============================ helpers =======================================
__device__ __forceinline__ uint32_t smem_u32(const void* p) {
    uint32_t a;
    asm("{ .reg .u64 t; cvta.to.shared.u64 t, %1; cvt.u32.u64 %0, t; }"
        : "=r"(a) : "l"(p));
    return a;
}
__device__ __forceinline__ uint32_t h2u(__half2 h) {
    return *reinterpret_cast<uint32_t*>(&h);
}
__device__ __forceinline__ uint4 cvt8(float4 v0, float4 v1) {
    uint4 w;
    w.x = h2u(__floats2half2_rn(v0.x, v0.y));
    w.y = h2u(__floats2half2_rn(v0.z, v0.w));
    w.z = h2u(__floats2half2_rn(v1.x, v1.y));
    w.w = h2u(__floats2half2_rn(v1.z, v1.w));
    return w;
}

#define CP16(dst, src) \
    asm volatile("cp.async.cg.shared.global [%0], [%1], 16;" \
                 :: "r"(dst), "l"(src) : "memory")
#define CP_COMMIT \
    asm volatile("cp.async.commit_group;" ::: "memory")
#define CP_WAIT(n) \
    asm volatile("cp.async.wait_group %0;" :: "n"(n) : "memory")

#define LDMX4(r, addr) \
    asm volatile("ldmatrix.sync.aligned.m8n8.x4.shared.b16 {%0,%1,%2,%3}, [%4];" \
                 : "=r"((r)[0]), "=r"((r)[1]), "=r"((r)[2]), "=r"((r)[3]) \
                 : "r"(addr))

#define LDMX4T(r, addr) \
    asm volatile("ldmatrix.sync.aligned.m8n8.x4.trans.shared.b16 {%0,%1,%2,%3}, [%4];" \
                 : "=r"((r)[0]), "=r"((r)[1]), "=r"((r)[2]), "=r"((r)[3]) \
                 : "r"(addr))

#define MMA16816(d, a, b) \
    asm volatile("mma.sync.aligned.m16n8k16.row.col.f32.f16.f16.f32 " \
                 "{%0,%1,%2,%3}, {%4,%5,%6,%7}, {%8,%9}, {%0,%1,%2,%3};" \
                 : "+f"((d)[0]), "+f"((d)[1]), "+f"((d)[2]), "+f"((d)[3]) \
                 : "r"((a)[0]), "r"((a)[1]), "r"((a)[2]), "r"((a)[3]), \
                   "r"((b)[0]), "r"((b)[1]))

// ======================= conversion kernels =================================
__global__ void __launch_bounds__(512)
cvt_msg_kernel(const float* __restrict__ msg, int total) {
    const int idx = blockIdx.x * 512 + threadIdx.x;   // one per 8 floats
    const int n = total * (HID / 8);
    if (idx >= n) return;
    const float4* p = (const float4*)msg + (size_t)idx * 2;
    ((uint4*)g_Xh)[idx] = cvt8(p[0], p[1]);
}

__global__ void __launch_bounds__(256)
cvt_w_kernel(const float* __restrict__ Wq, const float* __restrict__ Wk,
             const float* __restrict__ Wv, const float* __restrict__ Wo) {
    const int idx = blockIdx.x * 256 + threadIdx.x;   // 4*8192 groups of 8
    const int mat = idx >> 13;
    const int off = idx & 8191;
    const float* W = (mat == 0) ? Wq : (mat == 1 ? Wk : (mat == 2 ? Wv : Wo));
    const float4* p = (const float4*)W + (size_t)off * 2;
    ((uint4*)(g_Wh + mat * HID * HID))[off] = cvt8(p[0], p[1]);
}

// ======================= QKV GEMM (fp16 in, fp16 out) =======================
// Out[r][c] = sum_k X[r][k] * W[c][k]; 128x128 tile, 256 thr, warp 64x32.
// BK=64, 4 chunks, double-buffered cp.async (2 stages x (A+B) 72-stride).
#define LDC 72
#define CHUNK_HALVES (128 * LDC)
#define GEMM_SMEM (4 * CHUNK_HALVES * 2)   // 73728 B

__global__ void __launch_bounds__(256, 2)
qkv_mma_kernel(int total) {
    extern __shared__ __half sh[];

    const int bx = blockIdx.x;            // 0..5 fastest -> X-tile L2 reuse
    const int mat = bx >> 1;
    const int c0 = (bx & 1) * 128;
    const __half* __restrict__ Ah = g_Xh;
    const __half* __restrict__ Wh = g_Wh + mat * HID * HID;
    __half* __restrict__ OutH = (mat == 0) ? g_Qh : (mat == 1 ? g_Kh : g_Vh);
    const int row0 = blockIdx.y * 128;

    const int tid = threadIdx.x;
    const int lane = tid & 31;
    const int wid = tid >> 5;

    float acc[4][4][4];
#pragma unroll
    for (int f = 0; f < 4; f++)
#pragma unroll
        for (int j = 0; j < 4; j++)
#pragma unroll
            for (int e = 0; e < 4; e++) acc[f][j][e] = 0.f;

    const int srow = tid >> 1;            // 0..127
    const int sseg = (tid & 1) * 32;      // 32-half segment of the 64-chunk
    const uint32_t base0 = smem_u32(sh);
    const uint32_t stageA0 = base0;
    const uint32_t stageA1 = base0 + CHUNK_HALVES * 2;
    const uint32_t stageB0 = base0 + 2 * CHUNK_HALVES * 2;
    const uint32_t stageB1 = base0 + 3 * CHUNK_HALVES * 2;
    const uint32_t dOffs = (uint32_t)((srow * LDC + sseg) * 2);
    const __half* srcA = Ah + (size_t)(row0 + srow) * HID + sseg;
    const __half* srcB = Wh + (size_t)(c0 + srow) * HID + sseg;

    const int warp_m = (wid >> 2) * 64;
    const int warp_n = (wid & 3) * 32;
    const uint32_t aOff = (uint32_t)(((lane & 15) * LDC + (lane >> 4) * 8) * 2);
    const uint32_t bRow = (uint32_t)(((lane >> 4) << 3) + (lane & 7));
    const uint32_t bCol = (uint32_t)(((lane >> 3) & 1) * 8);

    // prologue: prefetch chunks 0 and 1
#pragma unroll
    for (int c = 0; c < 2; c++) {
        const uint32_t dA = (c == 0 ? stageA0 : stageA1) + dOffs;
        const uint32_t dB = (c == 0 ? stageB0 : stageB1) + dOffs;
#pragma unroll
        for (int j = 0; j < 4; j++) {     // 32 halves = 4 x 16B
            CP16(dA + j * 16, srcA + c * 64 + j * 8);
            CP16(dB + j * 16, srcB + c * 64 + j * 8);
        }
        CP_COMMIT;
    }

#pragma unroll
    for (int c = 0; c < 4; c++) {
        if (c < 3) CP_WAIT(1); else CP_WAIT(0);
        __syncthreads();

        const uint32_t aB = (c & 1) ? stageA1 : stageA0;
        const uint32_t bB = (c & 1) ? stageB1 : stageB0;

#pragma unroll
        for (int ks = 0; ks < 4; ks++) {
            uint32_t a[4][4];
            uint32_t b[4][2];
#pragma unroll
            for (int f = 0; f < 4; f++) {
                uint32_t addr = aB +
                    (uint32_t)(((warp_m + f * 16) * LDC + ks * 16) * 2) + aOff;
                LDMX4(a[f], addr);
            }
#pragma unroll
            for (int g = 0; g < 2; g++) {
                uint32_t addr = bB +
                    (uint32_t)(((warp_n + g * 16 + bRow) * LDC +
                                ks * 16 + bCol) * 2);
                uint32_t r[4];
                LDMX4(r, addr);
                b[2 * g][0] = r[0]; b[2 * g][1] = r[1];
                b[2 * g + 1][0] = r[2]; b[2 * g + 1][1] = r[3];
            }
#pragma unroll
            for (int f = 0; f < 4; f++)
#pragma unroll
                for (int j = 0; j < 4; j++)
                    MMA16816(acc[f][j], a[f], b[j]);
        }
        __syncthreads();

        if (c + 2 < 4) {
            const uint32_t dA = ((c & 1) ? stageA1 : stageA0) + dOffs;
            const uint32_t dB = ((c & 1) ? stageB1 : stageB0) + dOffs;
#pragma unroll
            for (int j = 0; j < 4; j++) {
                CP16(dA + j * 16, srcA + (c + 2) * 64 + j * 8);
                CP16(dB + j * 16, srcB + (c + 2) * 64 + j * 8);
            }
            CP_COMMIT;
        }
    }

#pragma unroll
    for (int f = 0; f < 4; f++) {
        const int row_lo = row0 + warp_m + f * 16 + (lane >> 2);
        const int row_hi = row_lo + 8;
#pragma unroll
        for (int j = 0; j < 4; j++) {
            const int col = c0 + warp_n + j * 8 + (lane & 3) * 2;
            if (row_lo < total)
                *(__half2*)(OutH + (size_t)row_lo * HID + col) =
                    __floats2half2_rn(acc[f][j][0], acc[f][j][1]);
            if (row_hi < total)
                *(__half2*)(OutH + (size_t)row_hi * HID + col) =
                    __floats2half2_rn(acc[f][j][2], acc[f][j][3]);
        }
    }
}

// ================ Flash attention (HMMA, online softmax) ====================
// CTA = (mol, head); 8 warps x 16 query rows; 32-key chunks.
// Staging: guarded LDG+STS, bounded to Sr = ceil(S/32)*32 tokens — rows >= Sr
// are never read by the compute loop (keys < nchunks*32 = Sr, queries < S).
#define LDQ 72
#define LDK 72
#define LDV 72
#define ATTN_SMEM (3 * 128 * LDQ * 2)

__global__ void __launch_bounds__(256, 3)
attn_mma_kernel(const int* __restrict__ b_starts,
                const int* __restrict__ b_sizes) {
    extern __shared__ __half ash[];
    __half* qS = ash;
    __half* kS = ash + 128 * LDQ;
    __half* vS = ash + 2 * 128 * LDQ;

    const int m = blockIdx.x;
    const int h = blockIdx.y;
    const int S = b_sizes[m];
    const int start = b_starts[m];
    const int tid = threadIdx.x;
    const int lane = tid & 31;
    const int wid = tid >> 5;          // 0..7
    const int Sr = (S + 31) & ~31;     // staged token bound

    // ---- stage Q, K, V row-major (zero in [S, Sr), nothing >= Sr) ----
    {
        const int tok = tid >> 1;
        if (tok < Sr) {
            const int seg = (tid & 1) * 32;
            const bool ok = tok < S;
            const __half* qp = g_Qh + (size_t)(start + tok) * HID + h * DH + seg;
            const __half* kp = g_Kh + (size_t)(start + tok) * HID + h * DH + seg;
            const __half* vp = g_Vh + (size_t)(start + tok) * HID + h * DH + seg;
            const uint4 z = make_uint4(0, 0, 0, 0);
#pragma unroll
            for (int j = 0; j < 4; j++) {   // 32 halves = 4 x uint4
                uint4 qv = ok ? ((const uint4*)qp)[j] : z;
                uint4 kv = ok ? ((const uint4*)kp)[j] : z;
                uint4 vv = ok ? ((const uint4*)vp)[j] : z;
                *(uint4*)(qS + tok * LDQ + seg + j * 8) = qv;
                *(uint4*)(kS + tok * LDK + seg + j * 8) = kv;
                *(uint4*)(vS + tok * LDV + seg + j * 8) = vv;
            }
        }
    }
    __syncthreads();

    const int wq0 = wid * 16;
    if (wq0 >= S) return;   // idle query warps exit (no more barriers below)

    const uint32_t qBase = smem_u32(qS);
    const uint32_t kBase = smem_u32(kS);
    const uint32_t vBase = smem_u32(vS);
    const uint32_t aOff = (uint32_t)(((lane & 15) * LDQ + (lane >> 4) * 8) * 2);
    const uint32_t bRow = (uint32_t)(((lane >> 4) << 3) + (lane & 7));
    const uint32_t bCol = (uint32_t)(((lane >> 3) & 1) * 8);
    // trans-load lane map for V: k-row and n(d)-offset
    const uint32_t vRow = (uint32_t)((lane & 7) + ((lane >> 3) & 1) * 8);
    const uint32_t vCol = (uint32_t)((lane >> 4) * 8);

    float oa[8][4];
#pragma unroll
    for (int dt = 0; dt < 8; dt++)
#pragma unroll
        for (int e = 0; e < 4; e++) oa[dt][e] = 0.f;
    float mx0 = -3.0e38f, mx1 = -3.0e38f;
    float ls0 = 0.f, ls1 = 0.f;

    const int nchunks = (S + 31) >> 5;
    for (int ch = 0; ch < nchunks; ch++) {
        const int key0 = ch * 32;

        float sacc[4][4];
#pragma unroll
        for (int n = 0; n < 4; n++)
#pragma unroll
            for (int e = 0; e < 4; e++) sacc[n][e] = 0.f;

#pragma unroll
        for (int kd = 0; kd < 4; kd++) {
            uint32_t qA[4];
            {
                uint32_t addr = qBase +
                    (uint32_t)((wq0 * LDQ + kd * 16) * 2) + aOff;
                LDMX4(qA, addr);
            }
            uint32_t bK[4][2];
#pragma unroll
            for (int g = 0; g < 2; g++) {
                uint32_t addr = kBase +
                    (uint32_t)(((key0 + g * 16 + bRow) * LDK + kd * 16 + bCol) * 2);
                uint32_t r[4];
                LDMX4(r, addr);
                bK[2 * g][0] = r[0]; bK[2 * g][1] = r[1];
                bK[2 * g + 1][0] = r[2]; bK[2 * g + 1][1] = r[3];
            }
#pragma unroll
            for (int n = 0; n < 4; n++)
                MMA16816(sacc[n], qA, bK[n]);
        }

        // ---- online softmax (rows lane>>2 and +8 of this 16-row block) ----
        uint32_t pA[2][4];
        {
            float sv[4][4];
#pragma unroll
            for (int n = 0; n < 4; n++) {
                const int cb = key0 + n * 8 + (lane & 3) * 2;
                const bool k0ok = cb < S;
                const bool k1ok = (cb + 1) < S;
                sv[n][0] = k0ok ? sacc[n][0] * 0.125f : -1.0e30f;
                sv[n][1] = k1ok ? sacc[n][1] * 0.125f : -1.0e30f;
                sv[n][2] = k0ok ? sacc[n][2] * 0.125f : -1.0e30f;
                sv[n][3] = k1ok ? sacc[n][3] * 0.125f : -1.0e30f;
            }
            float m0 = -3.0e38f, m1 = -3.0e38f;
#pragma unroll
            for (int n = 0; n < 4; n++) {
                m0 = fmaxf(m0, fmaxf(sv[n][0], sv[n][1]));
                m1 = fmaxf(m1, fmaxf(sv[n][2], sv[n][3]));
            }
            m0 = fmaxf(m0, __shfl_xor_sync(0xffffffffu, m0, 1));
            m0 = fmaxf(m0, __shfl_xor_sync(0xffffffffu, m0, 2));
            m1 = fmaxf(m1, __shfl_xor_sync(0xffffffffu, m1, 1));
            m1 = fmaxf(m1, __shfl_xor_sync(0xffffffffu, m1, 2));
            const float nm0 = fmaxf(mx0, m0);
            const float nm1 = fmaxf(mx1, m1);
            const float sc0 = __expf(mx0 - nm0);
            const float sc1 = __expf(mx1 - nm1);
            mx0 = nm0; mx1 = nm1;

            float e[4][4];
            float s0 = 0.f, s1 = 0.f;
#pragma unroll
            for (int n = 0; n < 4; n++) {
                e[n][0] = __expf(sv[n][0] - nm0);
                e[n][1] = __expf(sv[n][1] - nm0);
                e[n][2] = __expf(sv[n][2] - nm1);
                e[n][3] = __expf(sv[n][3] - nm1);
                s0 += e[n][0] + e[n][1];
                s1 += e[n][2] + e[n][3];
            }
            s0 += __shfl_xor_sync(0xffffffffu, s0, 1);
            s0 += __shfl_xor_sync(0xffffffffu, s0, 2);
            s1 += __shfl_xor_sync(0xffffffffu, s1, 1);
            s1 += __shfl_xor_sync(0xffffffffu, s1, 2);
            ls0 = ls0 * sc0 + s0;
            ls1 = ls1 * sc1 + s1;

#pragma unroll
            for (int dt = 0; dt < 8; dt++) {
                oa[dt][0] *= sc0; oa[dt][1] *= sc0;
                oa[dt][2] *= sc1; oa[dt][3] *= sc1;
            }
#pragma unroll
            for (int kk = 0; kk < 2; kk++) {
                pA[kk][0] = h2u(__floats2half2_rn(e[2 * kk][0], e[2 * kk][1]));
                pA[kk][1] = h2u(__floats2half2_rn(e[2 * kk][2], e[2 * kk][3]));
                pA[kk][2] = h2u(__floats2half2_rn(e[2 * kk + 1][0], e[2 * kk + 1][1]));
                pA[kk][3] = h2u(__floats2half2_rn(e[2 * kk + 1][2], e[2 * kk + 1][3]));
            }
        }

        // ---- O += P @ V  (B-fragments via ldmatrix.trans on row-major V) ----
#pragma unroll
        for (int kk = 0; kk < 2; kk++) {
            uint32_t bV[8][2];
#pragma unroll
            for (int g = 0; g < 4; g++) {
                uint32_t addr = vBase +
                    (uint32_t)(((key0 + kk * 16 + vRow) * LDV + g * 16 + vCol) * 2);
                uint32_t r[4];
                LDMX4T(r, addr);
                bV[2 * g][0] = r[0]; bV[2 * g][1] = r[1];
                bV[2 * g + 1][0] = r[2]; bV[2 * g + 1][1] = r[3];
            }
#pragma unroll
            for (int dt = 0; dt < 8; dt++)
                MMA16816(oa[dt], pA[kk], bV[dt]);
        }
    }

    // ---- store: ReLU(o / l) -> g_Oh ----
    {
        const float i0 = 1.0f / ls0;
        const float i1 = 1.0f / ls1;
        const int r = wq0 + (lane >> 2);
        const bool ok0 = r < S;
        const bool ok1 = (r + 8) < S;
#pragma unroll
        for (int dt = 0; dt < 8; dt++) {
            const int c = h * DH + dt * 8 + (lane & 3) * 2;
            if (ok0)
                *(__half2*)(g_Oh + (size_t)(start + r) * HID + c) =
                    __floats2half2_rn(fmaxf(oa[dt][0] * i0, 0.f),
                                      fmaxf(oa[dt][1] * i0, 0.f));
            if (ok1)
                *(__half2*)(g_Oh + (size_t)(start + r + 8) * HID + c) =
                    __floats2half2_rn(fmaxf(oa[dt][2] * i1, 0.f),
                                      fmaxf(oa[dt][3] * i1, 0.f));
        }
    }
}

// ============== Output projection + fused LayerNorm =========================
// 512 threads, 16 warps (4m x 4n), warp tile 32x64, BN=256 (full row / CTA).
// Both 128-K chunks double-buffered via cp.async (prefetched in prologue).
#define LDA 136
#define ST_HALVES ((128 + 256) * LDA)
#define PROJ_SMEM (2 * ST_HALVES * 2 + 4 * 128 * 2 * 4)

__global__ void __launch_bounds__(512, 1)
proj_ln_kernel(const float* __restrict__ bo,
               const float* __restrict__ gamma,
               const float* __restrict__ beta,
               float* __restrict__ out,
               int total) {
    extern __shared__ __half sh[];
    float* rsum = (float*)(sh + 2 * ST_HALVES);   // [4][128]
    float* rsq  = rsum + 4 * 128;                 // [4][128]

    const int row0 = blockIdx.x * 128;
    const int tid = threadIdx.x;
    const int lane = tid & 31;
    const int wid = tid >> 5;
    const __half* __restrict__ Wo16 = g_Wh + 3 * HID * HID;

    float acc[2][8][4];
#pragma unroll
    for (int f = 0; f < 2; f++)
#pragma unroll
        for (int j = 0; j < 8; j++)
#pragma unroll
            for (int e = 0; e < 4; e++) acc[f][j][e] = 0.f;

    const uint32_t sBase = smem_u32(sh);
    // A staging: thread -> row tid>>2, seg tid&3 (32 halves = 4 x 16B)
    const int arow = tid >> 2, aseg = tid & 3;
    const uint32_t aD = (uint32_t)((arow * LDA + aseg * 32) * 2);
    const __half* srcA = g_Oh + (size_t)(row0 + arow) * HID + aseg * 32;
    // B staging: thread -> row tid>>1, seg tid&1 (64 halves = 8 x 16B)
    const int brow = tid >> 1, bseg = tid & 1;
    const uint32_t bD = (uint32_t)((brow * LDA + bseg * 64) * 2) + 128 * LDA * 2;
    const __half* srcB = Wo16 + (size_t)brow * HID + bseg * 64;

    const int warp_m = (wid >> 2) * 32;
    const int warp_n = (wid & 3) * 64;
    const uint32_t aOff = (uint32_t)(((lane & 15) * LDA + (lane >> 4) * 8) * 2);
    const uint32_t bRow = (uint32_t)(((lane >> 4) << 3) + (lane & 7));
    const uint32_t bCol = (uint32_t)(((lane >> 3) & 1) * 8);

    // prologue: prefetch BOTH chunks (stages 0 and 1)
#pragma unroll
    for (int c = 0; c < 2; c++) {
        const uint32_t st = sBase + (uint32_t)(c * ST_HALVES * 2);
#pragma unroll
        for (int j = 0; j < 4; j++)
            CP16(st + aD + j * 16, srcA + c * 128 + j * 8);
#pragma unroll
        for (int j = 0; j < 8; j++)
            CP16(st + bD + j * 16, srcB + c * 128 + j * 8);
        CP_COMMIT;
    }

#pragma unroll
    for (int kc = 0; kc < 2; kc++) {
        if (kc == 0) CP_WAIT(1); else CP_WAIT(0);
        __syncthreads();

        const uint32_t aBase = sBase + (uint32_t)(kc * ST_HALVES * 2);
        const uint32_t bBase = aBase + 128 * LDA * 2;

#pragma unroll
        for (int ks = 0; ks < 8; ks++) {
            uint32_t a[2][4];
            uint32_t b[8][2];
#pragma unroll
            for (int f = 0; f < 2; f++) {
                uint32_t addr = aBase +
                    (uint32_t)(((warp_m + f * 16) * LDA + ks * 16) * 2) + aOff;
                LDMX4(a[f], addr);
            }
#pragma unroll
            for (int g = 0; g < 4; g++) {
                uint32_t addr = bBase +
                    (uint32_t)(((warp_n + g * 16 + bRow) * LDA +
                                ks * 16 + bCol) * 2);
                uint32_t r[4];
                LDMX4(r, addr);
                b[2 * g][0] = r[0]; b[2 * g][1] = r[1];
                b[2 * g + 1][0] = r[2]; b[2 * g + 1][1] = r[3];
            }
#pragma unroll
            for (int f = 0; f < 2; f++)
#pragma unroll
                for (int j = 0; j < 8; j++)
                    MMA16816(acc[f][j], a[f], b[j]);
        }
    }

    // ---- bias add + per-row partial sums ----
#pragma unroll
    for (int f = 0; f < 2; f++) {
        float sl = 0.f, ql = 0.f, shg = 0.f, qh = 0.f;
#pragma unroll
        for (int j = 0; j < 8; j++) {
            const int col = warp_n + j * 8 + (lane & 3) * 2;
            float2 bb = *(const float2*)(bo + col);
            acc[f][j][0] += bb.x; acc[f][j][1] += bb.y;
            acc[f][j][2] += bb.x; acc[f][j][3] += bb.y;
            sl += acc[f][j][0] + acc[f][j][1];
            ql += acc[f][j][0] * acc[f][j][0] + acc[f][j][1] * acc[f][j][1];
            shg += acc[f][j][2] + acc[f][j][3];
            qh += acc[f][j][2] * acc[f][j][2] + acc[f][j][3] * acc[f][j][3];
        }
        sl += __shfl_xor_sync(0xffffffffu, sl, 1);
        sl += __shfl_xor_sync(0xffffffffu, sl, 2);
        ql += __shfl_xor_sync(0xffffffffu, ql, 1);
        ql += __shfl_xor_sync(0xffffffffu, ql, 2);
        shg += __shfl_xor_sync(0xffffffffu, shg, 1);
        shg += __shfl_xor_sync(0xffffffffu, shg, 2);
        qh += __shfl_xor_sync(0xffffffffu, qh, 1);
        qh += __shfl_xor_sync(0xffffffffu, qh, 2);
        if ((lane & 3) == 0) {
            const int nw = wid & 3;
            const int rlo = warp_m + f * 16 + (lane >> 2);
            rsum[nw * 128 + rlo] = sl;
            rsq[nw * 128 + rlo] = ql;
            rsum[nw * 128 + rlo + 8] = shg;
            rsq[nw * 128 + rlo + 8] = qh;
        }
    }
    __syncthreads();

    // ---- LN + store ----
#pragma unroll
    for (int f = 0; f < 2; f++) {
        const int rlo = warp_m + f * 16 + (lane >> 2);
        const int rhi = rlo + 8;
        float s0 = rsum[rlo] + rsum[128 + rlo] + rsum[256 + rlo] + rsum[384 + rlo];
        float q0 = rsq[rlo] + rsq[128 + rlo] + rsq[256 + rlo] + rsq[384 + rlo];
        float s1 = rsum[rhi] + rsum[128 + rhi] + rsum[256 + rhi] + rsum[384 + rhi];
        float q1 = rsq[rhi] + rsq[128 + rhi] + rsq[256 + rhi] + rsq[384 + rhi];
        const float mu0 = s0 * (1.f / 256.f);
        const float mu1 = s1 * (1.f / 256.f);
        const float rs0 = rsqrtf(fmaxf(q0 * (1.f / 256.f) - mu0 * mu0, 0.f) + 1e-5f);
        const float rs1 = rsqrtf(fmaxf(q1 * (1.f / 256.f) - mu1 * mu1, 0.f) + 1e-5f);
        const int g_lo = row0 + rlo;
        const int g_hi = row0 + rhi;
        const bool ok0 = g_lo < total;
        const bool ok1 = g_hi < total;
        const bool z0 = (g_lo == 0);
#pragma unroll
        for (int j = 0; j < 8; j++) {
            const int col = warp_n + j * 8 + (lane & 3) * 2;
            float2 gg = *(const float2*)(gamma + col);
            float2 be = *(const float2*)(beta + col);
            if (ok0) {
                float2 v;
                if (z0) { v.x = 0.f; v.y = 0.f; }
                else {
                    v.x = (acc[f][j][0] - mu0) * rs0 * gg.x + be.x;
                    v.y = (acc[f][j][1] - mu0) * rs0 * gg.y + be.y;
                }
                *(float2*)(out + (size_t)g_lo * HID + col) = v;
            }
            if (ok1) {
                float2 v;
                v.x = (acc[f][j][2] - mu1) * rs1 * gg.x + be.x;
                v.y = (acc[f][j][3] - mu1) * rs1 * gg.y + be.y;
                *(float2*)(out + (size_t)g_hi * HID + col) = v;
            }
        }
    }
}

// ---------------------------------------------------------------------------
extern "C" void kernel_launch(void* const* d_in, const int* in_sizes, int n_in,
                              void* d_out, int out_size) {
    const float* msg      = (const float*)d_in[0];
    const float* Wq       = (const float*)d_in[1];
    const float* Wk       = (const float*)d_in[2];
    const float* Wv       = (const float*)d_in[3];
    const float* Wo       = (const float*)d_in[4];
    const float* bo       = (const float*)d_in[5];
    const float* gamma    = (const float*)d_in[6];
    const float* beta     = (const float*)d_in[7];
    const int*   b_starts = (const int*)d_in[8];
    const int*   b_sizes  = (const int*)d_in[9];
    float* out = (float*)d_out;

    const int total = in_sizes[0] / HID;
    const int tiles = (total + 127) / 128;

    cudaFuncSetAttribute(qkv_mma_kernel,
                         cudaFuncAttributeMaxDynamicSharedMemorySize, GEMM_SMEM);
    cudaFuncSetAttribute(attn_mma_kernel,
                         cudaFuncAttributeMaxDynamicSharedMemorySize, ATTN_SMEM);
    cudaFuncSetAttribute(proj_ln_kernel,
                         cudaFuncAttributeMaxDynamicSharedMemorySize, PROJ_SMEM);

    cvt_msg_kernel<<<(total * (HID / 8) + 511) / 512, 512>>>(msg, total);
    cvt_w_kernel<<<128, 256>>>(Wq, Wk, Wv, Wo);

    dim3 ga(6, tiles);
    qkv_mma_kernel<<<ga, 256, GEMM_SMEM>>>(total);

    dim3 gb(N_MOLS, NH);
    attn_mma_kernel<<<gb, 256, ATTN_SMEM>>>(b_starts, b_sizes);

    proj_ln_kernel<<<tiles, 512, PROJ_SMEM>>>(bo, gamma, beta, out, total);
}